// round 9
// baseline (speedup 1.0000x reference)
#include <cuda_runtime.h>
#include <cuda_fp16.h>
#include <cstdint>

#define NFEAT 64
#define NHID  256
#define EMAX  320000
#define AMAX  10000
#define BAMAX 40000
#define EPS_F 0.1f
#define COEF0 0.31415926535897931f   // pi / R0, R0 = 10
#define NTAB  4096
#define DMAX  10.0f
#define TSCALE ((float)NTAB / DMAX)
#define SLOT  (256 * 256)

// ---------------- scratch (device globals; no allocation allowed) ------------
__device__ __half g_te_h[(size_t)NTAB * 64];
__device__ __half g_te_l[(size_t)NTAB * 64];
__device__ __half g_xa_h[(size_t)BAMAX * 64];
__device__ __half g_xa_l[(size_t)BAMAX * 64];
__device__ __half g_t1h[(size_t)NTAB * NHID];
__device__ __half g_t1l[(size_t)NTAB * NHID];
__device__ __half g_t2h[(size_t)NTAB * NHID];
__device__ __half g_t2l[(size_t)NTAB * NHID];
__device__ __half g_a1h[(size_t)BAMAX * NHID];
__device__ __half g_a1l[(size_t)BAMAX * NHID];
__device__ __half g_a2h[(size_t)BAMAX * NHID];
__device__ __half g_a2l[(size_t)BAMAX * NHID];
__device__ __half g_tp[(size_t)NTAB * 64 * 8];    // paired table: [k][f] = {t_k[4], t_{k+1}[4]}
__device__ __half g_pk[(size_t)BAMAX * 64 * 8];   // packed row: [row][f] = {actv[4], v0,v1,v2,0}
__device__ float4 g_ep[EMAX];                     // per-edge (d0,d1,d2,idxf), edge order
__device__ float4 g_sep[EMAX];                    // sorted edge payload
__device__ int    g_sdst[EMAX];                   // sorted dst
__device__ __half g_wh[6 * SLOT];                 // transposed weight hi
__device__ int g_cnt[AMAX + 1];
__device__ int g_off[AMAX + 1];
__device__ int g_pos[AMAX];

// ---------------- PTX helpers -------------------------------------------------
__device__ __forceinline__ uint32_t smem_u32(const void* p) {
    uint32_t a;
    asm("{ .reg .u64 t; cvta.to.shared.u64 t, %1; cvt.u32.u64 %0, t; }" : "=r"(a) : "l"(p));
    return a;
}
#define CP16(saddr, gptr) \
    asm volatile("cp.async.cg.shared.global [%0], [%1], 16;" :: "r"(saddr), "l"(gptr) : "memory")
#define CP_COMMIT asm volatile("cp.async.commit_group;" ::: "memory")
#define CP_WAIT0 asm volatile("cp.async.wait_group 0;" ::: "memory")
#define CP_WAIT1 asm volatile("cp.async.wait_group 1;" ::: "memory")
#define CP_WAIT2 asm volatile("cp.async.wait_group 2;" ::: "memory")

__device__ __forceinline__ void ldsm_x4(uint32_t* r, uint32_t addr) {
    asm volatile("ldmatrix.sync.aligned.m8n8.x4.shared.b16 {%0,%1,%2,%3}, [%4];"
                 : "=r"(r[0]), "=r"(r[1]), "=r"(r[2]), "=r"(r[3]) : "r"(addr));
}
__device__ __forceinline__ void mma16816(float* c, const uint32_t* a, uint32_t b0, uint32_t b1) {
    asm volatile("mma.sync.aligned.m16n8k16.row.col.f32.f16.f16.f32 "
                 "{%0,%1,%2,%3}, {%4,%5,%6,%7}, {%8,%9}, {%0,%1,%2,%3};"
                 : "+f"(c[0]), "+f"(c[1]), "+f"(c[2]), "+f"(c[3])
                 : "r"(a[0]), "r"(a[1]), "r"(a[2]), "r"(a[3]), "r"(b0), "r"(b1));
}
__device__ __forceinline__ void split_h(float v, __half& h, __half& l) {
    h = __float2half_rn(v);
    l = __float2half_rn(v - __half2float(h));
}

// ---------------- prep: tencode + splits + wtrans + xv pack + edge prep + zero
__global__ void prep_kernel(
    const float* __restrict__ x_a, const float* __restrict__ x_v,
    const float* __restrict__ r_ij,
    const float* __restrict__ dW1, const float* __restrict__ dW2, const float* __restrict__ dW3,
    const float* __restrict__ aW1, const float* __restrict__ aW2, const float* __restrict__ aW3,
    int BA, int A, int E)
{
    const int tid = threadIdx.x;
    int bid = blockIdx.x;
    const int S0 = NTAB * 64 / 256;
    const int S1 = (BA * 64) / 256;
    const int SE = (E + 255) / 256;

    if (bid < S0) {
        int t = bid * 256 + tid;
        int k = t >> 6, j = t & 63;
        float d = (float)k * (DMAX / (float)NTAB);
        int kk = j & 31;
        float ph = (float)(1 + (kk >> 1)) * COEF0 * d;
        float v = (j < 32) ? cosf(ph) : sinf(ph);
        __half h, l;
        split_h(v, h, l);
        g_te_h[t] = h; g_te_l[t] = l;
        return;
    }
    bid -= S0;
    if (bid < S1) {
        int t = bid * 256 + tid;
        __half h, l;
        split_h(x_a[t], h, l);
        g_xa_h[t] = h; g_xa_l[t] = l;
        return;
    }
    bid -= S1;
    if (bid < S1) {   // x_v pack: [row][3] fp32 -> slots 4..7 of g_pk record
        int t = bid * 256 + tid;
        float v0 = x_v[(size_t)t * 3 + 0];
        float v1 = x_v[(size_t)t * 3 + 1];
        float v2 = x_v[(size_t)t * 3 + 2];
        __half2* dst2 = (__half2*)&g_pk[(size_t)t * 8 + 4];
        dst2[0] = __floats2half2_rn(v0, v1);
        dst2[1] = __floats2half2_rn(v2, 0.f);
        return;
    }
    bid -= S1;
    if (bid < SE) {   // edge precompute: direction + table index
        int t = bid * 256 + tid;
        if (t < E) {
            float rx = r_ij[(size_t)t * 3 + 0];
            float ry = r_ij[(size_t)t * 3 + 1];
            float rz = r_ij[(size_t)t * 3 + 2];
            float d2s = rx * rx + ry * ry + rz * rz;
            float d = sqrtf(d2s);
            float inv = rsqrtf(EPS_F + d2s);
            float idxf = d * TSCALE;
            if (idxf > (float)(NTAB - 1) - 1e-3f) idxf = (float)(NTAB - 1) - 1e-3f;
            g_ep[t] = make_float4(rx * inv, ry * inv, rz * inv, idxf);
        }
        return;
    }
    bid -= SE;
    if (bid < 1152) {
        const float* W; int K, slot;
        if      (bid < 64)  { W = dW1; K = 64;  slot = 0; }
        else if (bid < 320) { W = dW2; K = 256; slot = 1; bid -= 64; }
        else if (bid < 576) { W = dW3; K = 256; slot = 2; bid -= 320; }
        else if (bid < 640) { W = aW1; K = 64;  slot = 3; bid -= 576; }
        else if (bid < 896) { W = aW2; K = 256; slot = 4; bid -= 640; }
        else                { W = aW3; K = 256; slot = 5; bid -= 896; }
        int t = bid * 256 + tid;
        int n = t & 255, k = t >> 8;
        g_wh[(size_t)slot * SLOT + (size_t)n * K + k] =
            __float2half_rn(W[(size_t)k * 256 + n]);
        return;
    }
    bid -= 1152;
    int t = bid * 256 + tid;
    if (t <= A) g_cnt[t] = 0;
}

// ---------------- GEMM problem descriptor + body ------------------------------
// mode 0: fp16 hi/lo out; mode 2: actv -> g_pk slots 0..3; mode 3: table -> g_tp pair
struct GP {
    const __half* Ahi; const __half* Alo; int lda;
    const __half* Bhi;
    const float* bias;
    int M, K, act, mode;
    __half* OHi; __half* OLo;
};

#define HBK 32
#define ROWB 80    // 32 halves (64B) + 16B pad
#define A_HI_OFF 0
#define A_LO_OFF 10240
#define B_HI_OFF 20480
#define STAGE_SZ 30720

__device__ __forceinline__ void gemm_body(const GP p, int bx, int by) {
    extern __shared__ char smem[];
    const uint32_t sbase = smem_u32(smem);
    const int tid = threadIdx.x;
    const int lane = tid & 31;
    const int wid = tid >> 5;
    const int warp_m = wid & 3;
    const int warp_n = wid >> 2;
    const int row0 = bx * 128;
    const int col0 = by * 128;

    const uint32_t aoff = (uint32_t)(warp_m * 32 + (lane & 15)) * ROWB + ((lane >> 4) << 4);
    const uint32_t boff = (uint32_t)(warp_n * 64 + (lane & 7) + ((lane >> 4) << 3)) * ROWB
                        + (((lane >> 3) & 1) << 4);

    float acc[2][8][4];
#pragma unroll
    for (int tm = 0; tm < 2; tm++)
#pragma unroll
        for (int tn = 0; tn < 8; tn++)
#pragma unroll
            for (int j = 0; j < 4; j++) acc[tm][tn][j] = 0.f;

    const int NC = p.K / HBK;
    const int M = p.M;
    const int lda = p.lda;
    const int K = p.K;

    auto load_stage = [&](int buf, int kb) {
        const uint32_t sb = sbase + buf * STAGE_SZ;
#pragma unroll
        for (int it = 0; it < 2; it++) {
            int idx = tid + it * 256;
            int r = idx >> 2, cs = idx & 3;
            uint32_t so = (uint32_t)r * ROWB + cs * 16;
            size_t ga = (size_t)min(row0 + r, M - 1) * lda + kb + cs * 8;
            CP16(sb + A_HI_OFF + so, p.Ahi + ga);
            CP16(sb + A_LO_OFF + so, p.Alo + ga);
            size_t gb = (size_t)(col0 + r) * K + kb + cs * 8;
            CP16(sb + B_HI_OFF + so, p.Bhi + gb);
        }
    };

    // 3-stage pipeline
    load_stage(0, 0);
    CP_COMMIT;
    if (NC > 1) { load_stage(1, HBK); CP_COMMIT; }

    for (int c = 0; c < NC; c++) {
        if (c + 2 < NC) {
            __syncthreads();
            load_stage((c + 2) % 3, (c + 2) * HBK);
            CP_COMMIT;
        }
        int pend = NC - 1 - c;
        if (pend >= 2)      { CP_WAIT2; }
        else if (pend == 1) { CP_WAIT1; }
        else                { CP_WAIT0; }
        __syncthreads();
        const uint32_t sb = sbase + (c % 3) * STAGE_SZ;
        const uint32_t abase = sb + aoff;
        const uint32_t bbase = sb + B_HI_OFF + boff;
#pragma unroll
        for (int ks = 0; ks < 2; ks++) {
            uint32_t ah[2][4], al[2][4], bb[4][4];
            ldsm_x4(ah[0], abase + ks * 32);
            ldsm_x4(ah[1], abase + 16 * ROWB + ks * 32);
            ldsm_x4(al[0], abase + A_LO_OFF + ks * 32);
            ldsm_x4(al[1], abase + A_LO_OFF + 16 * ROWB + ks * 32);
#pragma unroll
            for (int tg = 0; tg < 4; tg++)
                ldsm_x4(bb[tg], bbase + tg * 16 * ROWB + ks * 32);
#pragma unroll
            for (int tm = 0; tm < 2; tm++)
#pragma unroll
                for (int tn = 0; tn < 8; tn++) {
                    uint32_t b0 = bb[tn >> 1][(tn & 1) * 2];
                    uint32_t b1 = bb[tn >> 1][(tn & 1) * 2 + 1];
                    mma16816(acc[tm][tn], ah[tm], b0, b1);
                    mma16816(acc[tm][tn], al[tm], b0, b1);
                }
        }
    }

#pragma unroll
    for (int tm = 0; tm < 2; tm++)
#pragma unroll
        for (int tn = 0; tn < 8; tn++) {
            int r0 = row0 + warp_m * 32 + tm * 16 + (lane >> 2);
            int col = col0 + warp_n * 64 + tn * 8 + 2 * (lane & 3);
            float b0 = __ldg(&p.bias[col]);
            float b1 = __ldg(&p.bias[col + 1]);
            float v0 = acc[tm][tn][0] + b0;
            float v1 = acc[tm][tn][1] + b1;
            float v2 = acc[tm][tn][2] + b0;
            float v3 = acc[tm][tn][3] + b1;
            if (p.act) {
                v0 = v0 / (1.f + __expf(-v0));
                v1 = v1 / (1.f + __expf(-v1));
                v2 = v2 / (1.f + __expf(-v2));
                v3 = v3 / (1.f + __expf(-v3));
            }
            if (p.mode == 0) {
                __half h0, l0, h1, l1;
                if (r0 < M) {
                    split_h(v0, h0, l0); split_h(v1, h1, l1);
                    *(__half2*)&p.OHi[(size_t)r0 * 256 + col] = __halves2half2(h0, h1);
                    *(__half2*)&p.OLo[(size_t)r0 * 256 + col] = __halves2half2(l0, l1);
                }
                if (r0 + 8 < M) {
                    split_h(v2, h0, l0); split_h(v3, h1, l1);
                    *(__half2*)&p.OHi[(size_t)(r0 + 8) * 256 + col] = __halves2half2(h0, h1);
                    *(__half2*)&p.OLo[(size_t)(r0 + 8) * 256 + col] = __halves2half2(l0, l1);
                }
            } else {
                int f = col & 63;
                int role = col >> 6;
                if (p.mode == 2) {   // actv -> g_pk record slots 0..3
                    if (r0 < M) {
                        g_pk[((size_t)r0 * 64 + f) * 8 + role]     = __float2half_rn(v0);
                        g_pk[((size_t)r0 * 64 + f + 1) * 8 + role] = __float2half_rn(v1);
                    }
                    if (r0 + 8 < M) {
                        g_pk[((size_t)(r0 + 8) * 64 + f) * 8 + role]     = __float2half_rn(v2);
                        g_pk[((size_t)(r0 + 8) * 64 + f + 1) * 8 + role] = __float2half_rn(v3);
                    }
                } else {             // mode 3: table pair -> g_tp rows k (lo) and k-1 (hi)
                    if (r0 < M) {
                        __half h0 = __float2half_rn(v0);
                        __half h1 = __float2half_rn(v1);
                        g_tp[((size_t)r0 * 64 + f) * 8 + role]     = h0;
                        g_tp[((size_t)r0 * 64 + f + 1) * 8 + role] = h1;
                        if (r0 > 0) {
                            g_tp[((size_t)(r0 - 1) * 64 + f) * 8 + 4 + role]     = h0;
                            g_tp[((size_t)(r0 - 1) * 64 + f + 1) * 8 + 4 + role] = h1;
                        }
                    }
                    if (r0 + 8 < M) {
                        __half h2 = __float2half_rn(v2);
                        __half h3 = __float2half_rn(v3);
                        g_tp[((size_t)(r0 + 8) * 64 + f) * 8 + role]     = h2;
                        g_tp[((size_t)(r0 + 8) * 64 + f + 1) * 8 + role] = h3;
                        g_tp[((size_t)(r0 + 7) * 64 + f) * 8 + 4 + role]     = h2;
                        g_tp[((size_t)(r0 + 7) * 64 + f + 1) * 8 + 4 + role] = h3;
                    }
                }
            }
        }
}

// ---------------- single-block exclusive scan (device body) -------------------
__device__ void scan_body(int A) {
    __shared__ int sh[256];
    int tid = threadIdx.x;
    int chunk = (A + 255) >> 8;
    int base = tid * chunk;
    int sum = 0;
    for (int j = 0; j < chunk; j++) {
        int idx = base + j;
        if (idx < A) sum += g_cnt[idx];
    }
    sh[tid] = sum;
    __syncthreads();
    for (int off = 1; off < 256; off <<= 1) {
        int v = 0;
        if (tid >= off) v = sh[tid - off];
        __syncthreads();
        sh[tid] += v;
        __syncthreads();
    }
    int run = (tid == 0) ? 0 : sh[tid - 1];
    for (int j = 0; j < chunk; j++) {
        int idx = base + j;
        if (idx < A) {
            g_off[idx] = run;
            g_pos[idx] = run;
            run += g_cnt[idx];
        }
    }
    if (base < A && A <= base + chunk) g_off[A] = run;
}

// ---------------- merged layer kernel: 2 GEMM problems + sort-step aux CTAs ---
__global__ void __launch_bounds__(256, 2) layer_kernel(
    GP pa, GP pt, int nA2, int nT2,
    int aux, const int* __restrict__ src, const int* __restrict__ dst, int E, int A)
{
    int bid = blockIdx.x;
    const int nG = nA2 + nT2;
    if (bid < nG) {
        bool isA = bid < nA2;
        GP p = isA ? pa : pt;
        int lb = isA ? bid : bid - nA2;
        gemm_body(p, lb >> 1, lb & 1);
        return;
    }
    int abid = bid - nG;
    int tid = threadIdx.x;
    if (aux == 1) {
        for (int t = abid * 256 + tid; t < E; t += 128 * 256)
            atomicAdd(&g_cnt[src[t]], 1);
    } else if (aux == 2) {
        scan_body(A);
    } else if (aux == 3) {
        // scatter edge PAYLOAD into sorted order (no index indirection later)
        for (int t = abid * 256 + tid; t < E; t += 128 * 256) {
            int pp = atomicAdd(&g_pos[src[t]], 1);
            g_sep[pp] = g_ep[t];
            g_sdst[pp] = dst[t];
        }
    }
}

// ---------------- per-atom gather: sequential payload + 16B gathers -----------
__global__ __launch_bounds__(256) void gather_kernel(
    const uint4* __restrict__ TP,           // g_tp: [k][f] = {t_k, t_{k+1}} 8 halves
    const uint4* __restrict__ PK,           // g_pk: [row][f] = {actv[4], v0..v2} 8 halves
    const float4* __restrict__ SEP,         // sorted (d0,d1,d2,idxf)
    const int* __restrict__ SDST,           // sorted dst
    float* __restrict__ out_a, float* __restrict__ out_v, int A)
{
    int a = blockIdx.x;
    int f = threadIdx.x & 63;
    int b = threadIdx.x >> 6;
    int p0 = g_off[a];
    int p1 = g_off[a + 1];

    float av0 = 0.f, av1 = 0.f, av2 = 0.f, aa = 0.f;
#pragma unroll 2
    for (int p = p0; p < p1; ++p) {
        float4 ed = __ldg(&SEP[p]);
        int dd = __ldg(&SDST[p]);
        float d0 = ed.x, d1 = ed.y, d2 = ed.z;
        int k = (int)ed.w;
        float w = ed.w - (float)k;

        uint4 tv = __ldg(&TP[(size_t)k * 64 + f]);
        float2 t0a = __half22float2(*(__half2*)&tv.x);
        float2 t0b = __half22float2(*(__half2*)&tv.y);
        float2 t1a = __half22float2(*(__half2*)&tv.z);
        float2 t1b = __half22float2(*(__half2*)&tv.w);
        float q0 = fmaf(w, t1a.x - t0a.x, t0a.x);
        float q1 = fmaf(w, t1a.y - t0a.y, t0a.y);
        float q2 = fmaf(w, t1b.x - t0b.x, t0b.x);
        float q3 = fmaf(w, t1b.y - t0b.y, t0b.y);

        uint4 pk = __ldg(&PK[(size_t)(b * A + dd) * 64 + f]);
        __half2 pra = *(__half2*)&pk.x;
        __half2 prb = *(__half2*)&pk.y;
        q0 *= __low2float(pra);
        q1 *= __high2float(pra);
        q2 *= __low2float(prb);
        q3 *= __high2float(prb);

        float2 va = __half22float2(*(__half2*)&pk.z);
        float v2f = __low2float(*(__half2*)&pk.w);
        float v0 = va.x, v1 = va.y, v2 = v2f;
        float c0 = v1 * d2 - v2 * d1;
        float c1 = v2 * d0 - v0 * d2;
        float c2 = v0 * d1 - v1 * d0;
        av0 += v0 * q0 + c0 * q1 + d0 * q2;
        av1 += v1 * q0 + c1 * q1 + d1 * q2;
        av2 += v2 * q0 + c2 * q1 + d2 * q2;
        aa  += q3;
    }
    out_a[(size_t)(b * A + a) * 64 + f] = aa;
    float* OV = out_v + (size_t)((b * A + a) * 64 + f) * 3;
    OV[0] = av0;
    OV[1] = av1;
    OV[2] = av2;
}

// ---------------- launch ------------------------------------------------------
extern "C" void kernel_launch(void* const* d_in, const int* in_sizes, int n_in,
                              void* d_out, int out_size) {
    const float* x_a  = (const float*)d_in[0];
    const float* x_v  = (const float*)d_in[1];
    const float* r_ij = (const float*)d_in[2];
    const int*   src  = (const int*)d_in[3];
    const int*   dst  = (const int*)d_in[4];
    const float* dW1 = (const float*)d_in[5];
    const float* db1 = (const float*)d_in[6];
    const float* dW2 = (const float*)d_in[7];
    const float* db2 = (const float*)d_in[8];
    const float* dW3 = (const float*)d_in[9];
    const float* db3 = (const float*)d_in[10];
    const float* aW1 = (const float*)d_in[11];
    const float* ab1 = (const float*)d_in[12];
    const float* aW2 = (const float*)d_in[13];
    const float* ab2 = (const float*)d_in[14];
    const float* aW3 = (const float*)d_in[15];
    const float* ab3 = (const float*)d_in[16];

    const int E  = in_sizes[3];
    const int BA = in_sizes[0] / NFEAT;
    const int A  = BA / 4;                 // B = 4

    __half *te_h, *te_l, *xa_h, *xa_l;
    __half *t1h, *t1l, *t2h, *t2l, *a1h, *a1l, *a2h, *a2l;
    __half *wh, *tp, *pk;
    float4 *sep;
    int *sdst;
    cudaGetSymbolAddress((void**)&te_h, g_te_h);
    cudaGetSymbolAddress((void**)&te_l, g_te_l);
    cudaGetSymbolAddress((void**)&xa_h, g_xa_h);
    cudaGetSymbolAddress((void**)&xa_l, g_xa_l);
    cudaGetSymbolAddress((void**)&t1h, g_t1h);
    cudaGetSymbolAddress((void**)&t1l, g_t1l);
    cudaGetSymbolAddress((void**)&t2h, g_t2h);
    cudaGetSymbolAddress((void**)&t2l, g_t2l);
    cudaGetSymbolAddress((void**)&a1h, g_a1h);
    cudaGetSymbolAddress((void**)&a1l, g_a1l);
    cudaGetSymbolAddress((void**)&a2h, g_a2h);
    cudaGetSymbolAddress((void**)&a2l, g_a2l);
    cudaGetSymbolAddress((void**)&wh, g_wh);
    cudaGetSymbolAddress((void**)&tp, g_tp);
    cudaGetSymbolAddress((void**)&pk, g_pk);
    cudaGetSymbolAddress((void**)&sep, g_sep);
    cudaGetSymbolAddress((void**)&sdst, g_sdst);

    cudaFuncSetAttribute(layer_kernel, cudaFuncAttributeMaxDynamicSharedMemorySize, 3 * STAGE_SZ);

    // 1) prep
    const int S1 = (BA * 64) / 256;
    const int SE = (E + 255) / 256;
    const int prep_blocks = (NTAB * 64 / 256) + 2 * S1 + SE + 1152 + (A + 1 + 255) / 256;
    prep_kernel<<<prep_blocks, 256>>>(x_a, x_v, r_ij, dW1, dW2, dW3, aW1, aW2, aW3, BA, A, E);

    const int nA2 = 2 * ((BA + 127) / 128);
    const int nT2 = 2 * (NTAB / 128);

    // 2) layer 1 (K=64) + hist
    {
        GP pa = { xa_h, xa_l, 64, wh + 3 * SLOT, ab1, BA, 64, 1, 0, a1h, a1l };
        GP pt = { te_h, te_l, 64, wh + 0 * SLOT, db1, NTAB, 64, 1, 0, t1h, t1l };
        layer_kernel<<<nA2 + nT2 + 128, 256, 3 * STAGE_SZ>>>(pa, pt, nA2, nT2, 1, src, dst, E, A);
    }
    // 3) layer 2 (K=256) + scan
    {
        GP pa = { a1h, a1l, 256, wh + 4 * SLOT, ab2, BA, 256, 1, 0, a2h, a2l };
        GP pt = { t1h, t1l, 256, wh + 1 * SLOT, db2, NTAB, 256, 1, 0, t2h, t2l };
        layer_kernel<<<nA2 + nT2 + 1, 256, 3 * STAGE_SZ>>>(pa, pt, nA2, nT2, 2, src, dst, E, A);
    }
    // 4) layer 3 (K=256, no act) + payload scatter; outputs g_pk (actv) / g_tp (table pair)
    {
        GP pa = { a2h, a2l, 256, wh + 5 * SLOT, ab3, BA, 256, 0, 2, nullptr, nullptr };
        GP pt = { t2h, t2l, 256, wh + 2 * SLOT, db3, NTAB, 256, 0, 3, nullptr, nullptr };
        layer_kernel<<<nA2 + nT2 + 128, 256, 3 * STAGE_SZ>>>(pa, pt, nA2, nT2, 3, src, dst, E, A);
    }

    // 5) gather
    float* out_a = (float*)d_out;
    float* out_v = (float*)d_out + (size_t)BA * NFEAT;
    gather_kernel<<<A, 256>>>((const uint4*)tp, (const uint4*)pk,
                              (const float4*)sep, (const int*)sdst, out_a, out_v, A);
}

// round 10
// speedup vs baseline: 1.0682x; 1.0682x over previous
#include <cuda_runtime.h>
#include <cuda_fp16.h>
#include <cstdint>

#define NFEAT 64
#define NHID  256
#define EMAX  320000
#define AMAX  10000
#define BAMAX 40000
#define EPS_F 0.1f
#define COEF0 0.31415926535897931f   // pi / R0, R0 = 10
#define NTAB  4096
#define DMAX  10.0f
#define TSCALE ((float)NTAB / DMAX)
#define SLOT  (256 * 256)

// ---------------- scratch (device globals; no allocation allowed) ------------
__device__ __half g_te_h[(size_t)NTAB * 64];
__device__ __half g_te_l[(size_t)NTAB * 64];
__device__ __half g_xa_h[(size_t)BAMAX * 64];
__device__ __half g_xa_l[(size_t)BAMAX * 64];
__device__ __half g_t1h[(size_t)NTAB * NHID];
__device__ __half g_t1l[(size_t)NTAB * NHID];
__device__ __half g_t2h[(size_t)NTAB * NHID];
__device__ __half g_t2l[(size_t)NTAB * NHID];
__device__ __half g_a1h[(size_t)BAMAX * NHID];
__device__ __half g_a1l[(size_t)BAMAX * NHID];
__device__ __half g_a2h[(size_t)BAMAX * NHID];
__device__ __half g_a2l[(size_t)BAMAX * NHID];
__device__ __half g_tp[(size_t)NTAB * 64 * 8];    // paired table: [k][f] = {t_k[4], t_{k+1}[4]}
__device__ __half g_pk[(size_t)BAMAX * 64 * 8];   // packed row: [row][f] = {actv[4], v0,v1,v2,0}
__device__ float4 g_ep[EMAX];                     // per-edge (d0,d1,d2,idxf), edge order
__device__ float4 g_sep[EMAX];                    // sorted edge payload
__device__ int    g_sdst[EMAX];                   // sorted dst
__device__ __half g_wh[6 * SLOT];                 // transposed weight hi
__device__ int g_cnt[AMAX + 1];
__device__ int g_off[AMAX + 1];
__device__ int g_pos[AMAX];

// ---------------- PTX helpers -------------------------------------------------
__device__ __forceinline__ uint32_t smem_u32(const void* p) {
    uint32_t a;
    asm("{ .reg .u64 t; cvta.to.shared.u64 t, %1; cvt.u32.u64 %0, t; }" : "=r"(a) : "l"(p));
    return a;
}
#define CP16(saddr, gptr) \
    asm volatile("cp.async.cg.shared.global [%0], [%1], 16;" :: "r"(saddr), "l"(gptr) : "memory")
#define CP_COMMIT asm volatile("cp.async.commit_group;" ::: "memory")
#define CP_WAIT0 asm volatile("cp.async.wait_group 0;" ::: "memory")
#define CP_WAIT1 asm volatile("cp.async.wait_group 1;" ::: "memory")
#define CP_WAIT2 asm volatile("cp.async.wait_group 2;" ::: "memory")

__device__ __forceinline__ void ldsm_x4(uint32_t* r, uint32_t addr) {
    asm volatile("ldmatrix.sync.aligned.m8n8.x4.shared.b16 {%0,%1,%2,%3}, [%4];"
                 : "=r"(r[0]), "=r"(r[1]), "=r"(r[2]), "=r"(r[3]) : "r"(addr));
}
__device__ __forceinline__ void mma16816(float* c, const uint32_t* a, uint32_t b0, uint32_t b1) {
    asm volatile("mma.sync.aligned.m16n8k16.row.col.f32.f16.f16.f32 "
                 "{%0,%1,%2,%3}, {%4,%5,%6,%7}, {%8,%9}, {%0,%1,%2,%3};"
                 : "+f"(c[0]), "+f"(c[1]), "+f"(c[2]), "+f"(c[3])
                 : "r"(a[0]), "r"(a[1]), "r"(a[2]), "r"(a[3]), "r"(b0), "r"(b1));
}
__device__ __forceinline__ void split_h(float v, __half& h, __half& l) {
    h = __float2half_rn(v);
    l = __float2half_rn(v - __half2float(h));
}

// ---------------- prep: tencode + splits + wtrans + xv pack + edge prep + zero
__global__ void prep_kernel(
    const float* __restrict__ x_a, const float* __restrict__ x_v,
    const float* __restrict__ r_ij,
    const float* __restrict__ dW1, const float* __restrict__ dW2, const float* __restrict__ dW3,
    const float* __restrict__ aW1, const float* __restrict__ aW2, const float* __restrict__ aW3,
    int BA, int A, int E)
{
    const int tid = threadIdx.x;
    int bid = blockIdx.x;
    const int S0 = NTAB * 64 / 256;
    const int S1 = (BA * 64) / 256;
    const int SE = (E + 255) / 256;

    if (bid < S0) {
        int t = bid * 256 + tid;
        int k = t >> 6, j = t & 63;
        float d = (float)k * (DMAX / (float)NTAB);
        int kk = j & 31;
        float ph = (float)(1 + (kk >> 1)) * COEF0 * d;
        float v = (j < 32) ? cosf(ph) : sinf(ph);
        __half h, l;
        split_h(v, h, l);
        g_te_h[t] = h; g_te_l[t] = l;
        return;
    }
    bid -= S0;
    if (bid < S1) {
        int t = bid * 256 + tid;
        __half h, l;
        split_h(x_a[t], h, l);
        g_xa_h[t] = h; g_xa_l[t] = l;
        return;
    }
    bid -= S1;
    if (bid < S1) {   // x_v pack: [row][3] fp32 -> slots 4..7 of g_pk record
        int t = bid * 256 + tid;
        float v0 = x_v[(size_t)t * 3 + 0];
        float v1 = x_v[(size_t)t * 3 + 1];
        float v2 = x_v[(size_t)t * 3 + 2];
        __half2* dst2 = (__half2*)&g_pk[(size_t)t * 8 + 4];
        dst2[0] = __floats2half2_rn(v0, v1);
        dst2[1] = __floats2half2_rn(v2, 0.f);
        return;
    }
    bid -= S1;
    if (bid < SE) {   // edge precompute: direction + table index
        int t = bid * 256 + tid;
        if (t < E) {
            float rx = r_ij[(size_t)t * 3 + 0];
            float ry = r_ij[(size_t)t * 3 + 1];
            float rz = r_ij[(size_t)t * 3 + 2];
            float d2s = rx * rx + ry * ry + rz * rz;
            float d = sqrtf(d2s);
            float inv = rsqrtf(EPS_F + d2s);
            float idxf = d * TSCALE;
            if (idxf > (float)(NTAB - 1) - 1e-3f) idxf = (float)(NTAB - 1) - 1e-3f;
            g_ep[t] = make_float4(rx * inv, ry * inv, rz * inv, idxf);
        }
        return;
    }
    bid -= SE;
    if (bid < 1152) {
        const float* W; int K, slot;
        if      (bid < 64)  { W = dW1; K = 64;  slot = 0; }
        else if (bid < 320) { W = dW2; K = 256; slot = 1; bid -= 64; }
        else if (bid < 576) { W = dW3; K = 256; slot = 2; bid -= 320; }
        else if (bid < 640) { W = aW1; K = 64;  slot = 3; bid -= 576; }
        else if (bid < 896) { W = aW2; K = 256; slot = 4; bid -= 640; }
        else                { W = aW3; K = 256; slot = 5; bid -= 896; }
        int t = bid * 256 + tid;
        int n = t & 255, k = t >> 8;
        g_wh[(size_t)slot * SLOT + (size_t)n * K + k] =
            __float2half_rn(W[(size_t)k * 256 + n]);
        return;
    }
    bid -= 1152;
    int t = bid * 256 + tid;
    if (t <= A) g_cnt[t] = 0;
}

// ---------------- GEMM problem descriptor + body ------------------------------
// mode 0: fp16 hi/lo out; mode 2: actv -> g_pk role-words; mode 3: table -> g_tp pair
struct GP {
    const __half* Ahi; const __half* Alo; int lda;
    const __half* Bhi;
    const float* bias;
    int M, K, act, mode;
    __half* OHi; __half* OLo;
};

#define HBK 32
#define ROWB 80    // 32 halves (64B) + 16B pad
#define A_HI_OFF 0
#define A_LO_OFF 10240
#define B_HI_OFF 20480
#define STAGE_SZ 30720
#define SPH 136    // staging pitch in halves (272B per row of 128 halves + pad)

__device__ __forceinline__ void gemm_body(const GP p, int bx, int by) {
    extern __shared__ char smem[];
    const uint32_t sbase = smem_u32(smem);
    const int tid = threadIdx.x;
    const int lane = tid & 31;
    const int wid = tid >> 5;
    const int warp_m = wid & 3;
    const int warp_n = wid >> 2;
    const int row0 = bx * 128;
    const int col0 = by * 128;

    const uint32_t aoff = (uint32_t)(warp_m * 32 + (lane & 15)) * ROWB + ((lane >> 4) << 4);
    const uint32_t boff = (uint32_t)(warp_n * 64 + (lane & 7) + ((lane >> 4) << 3)) * ROWB
                        + (((lane >> 3) & 1) << 4);

    float acc[2][8][4];
#pragma unroll
    for (int tm = 0; tm < 2; tm++)
#pragma unroll
        for (int tn = 0; tn < 8; tn++)
#pragma unroll
            for (int j = 0; j < 4; j++) acc[tm][tn][j] = 0.f;

    const int NC = p.K / HBK;
    const int M = p.M;
    const int lda = p.lda;
    const int K = p.K;

    auto load_stage = [&](int buf, int kb) {
        const uint32_t sb = sbase + buf * STAGE_SZ;
#pragma unroll
        for (int it = 0; it < 2; it++) {
            int idx = tid + it * 256;
            int r = idx >> 2, cs = idx & 3;
            uint32_t so = (uint32_t)r * ROWB + cs * 16;
            size_t ga = (size_t)min(row0 + r, M - 1) * lda + kb + cs * 8;
            CP16(sb + A_HI_OFF + so, p.Ahi + ga);
            CP16(sb + A_LO_OFF + so, p.Alo + ga);
            size_t gb = (size_t)(col0 + r) * K + kb + cs * 8;
            CP16(sb + B_HI_OFF + so, p.Bhi + gb);
        }
    };

    // 3-stage pipeline
    load_stage(0, 0);
    CP_COMMIT;
    if (NC > 1) { load_stage(1, HBK); CP_COMMIT; }

    for (int c = 0; c < NC; c++) {
        if (c + 2 < NC) {
            __syncthreads();
            load_stage((c + 2) % 3, (c + 2) * HBK);
            CP_COMMIT;
        }
        int pend = NC - 1 - c;
        if (pend >= 2)      { CP_WAIT2; }
        else if (pend == 1) { CP_WAIT1; }
        else                { CP_WAIT0; }
        __syncthreads();
        const uint32_t sb = sbase + (c % 3) * STAGE_SZ;
        const uint32_t abase = sb + aoff;
        const uint32_t bbase = sb + B_HI_OFF + boff;
#pragma unroll
        for (int ks = 0; ks < 2; ks++) {
            uint32_t ah[2][4], al[2][4], bb[4][4];
            ldsm_x4(ah[0], abase + ks * 32);
            ldsm_x4(ah[1], abase + 16 * ROWB + ks * 32);
            ldsm_x4(al[0], abase + A_LO_OFF + ks * 32);
            ldsm_x4(al[1], abase + A_LO_OFF + 16 * ROWB + ks * 32);
#pragma unroll
            for (int tg = 0; tg < 4; tg++)
                ldsm_x4(bb[tg], bbase + tg * 16 * ROWB + ks * 32);
#pragma unroll
            for (int tm = 0; tm < 2; tm++)
#pragma unroll
                for (int tn = 0; tn < 8; tn++) {
                    uint32_t b0 = bb[tn >> 1][(tn & 1) * 2];
                    uint32_t b1 = bb[tn >> 1][(tn & 1) * 2 + 1];
                    mma16816(acc[tm][tn], ah[tm], b0, b1);
                    mma16816(acc[tm][tn], al[tm], b0, b1);
                }
        }
    }

    __half* sg = (__half*)smem;   // staging reuse (modes 2/3)
    if (p.mode != 0) __syncthreads();   // pipeline smem now safe to reuse

#pragma unroll
    for (int tm = 0; tm < 2; tm++)
#pragma unroll
        for (int tn = 0; tn < 8; tn++) {
            int rl = warp_m * 32 + tm * 16 + (lane >> 2);   // local row 0..127
            int col = warp_n * 64 + tn * 8 + 2 * (lane & 3); // local col 0..127
            int r0 = row0 + rl;
            int gcol = col0 + col;
            float b0 = __ldg(&p.bias[gcol]);
            float b1 = __ldg(&p.bias[gcol + 1]);
            float v0 = acc[tm][tn][0] + b0;
            float v1 = acc[tm][tn][1] + b1;
            float v2 = acc[tm][tn][2] + b0;
            float v3 = acc[tm][tn][3] + b1;
            if (p.act) {
                v0 = v0 / (1.f + __expf(-v0));
                v1 = v1 / (1.f + __expf(-v1));
                v2 = v2 / (1.f + __expf(-v2));
                v3 = v3 / (1.f + __expf(-v3));
            }
            if (p.mode == 0) {
                __half h0, l0, h1, l1;
                if (r0 < M) {
                    split_h(v0, h0, l0); split_h(v1, h1, l1);
                    *(__half2*)&p.OHi[(size_t)r0 * 256 + gcol] = __halves2half2(h0, h1);
                    *(__half2*)&p.OLo[(size_t)r0 * 256 + gcol] = __halves2half2(l0, l1);
                }
                if (r0 + 8 < M) {
                    split_h(v2, h0, l0); split_h(v3, h1, l1);
                    *(__half2*)&p.OHi[(size_t)(r0 + 8) * 256 + gcol] = __halves2half2(h0, h1);
                    *(__half2*)&p.OLo[(size_t)(r0 + 8) * 256 + gcol] = __halves2half2(l0, l1);
                }
            } else {
                // stage into smem: per (row, f) a 4B word holding our 2 roles
                int f = col & 63;
                int rlo = (col >> 6) & 1;       // local role index within our pair
                sg[rl * SPH + f * 2 + rlo]           = __float2half_rn(v0);
                sg[rl * SPH + (f + 1) * 2 + rlo]     = __float2half_rn(v1);
                sg[(rl + 8) * SPH + f * 2 + rlo]     = __float2half_rn(v2);
                sg[(rl + 8) * SPH + (f + 1) * 2 + rlo] = __float2half_rn(v3);
            }
        }

    if (p.mode >= 2) {
        __syncthreads();
        const int by4 = by * 4;    // byte offset of our role-pair word within record
        if (p.mode == 2) {
            // g_pk record 16B: [0,4)=roles01, [4,8)=roles23, [8,16)=xv (prep)
#pragma unroll
            for (int i = 0; i < 32; i++) {
                int idx = tid + i * 256;
                int rr = idx >> 6, f = idx & 63;
                int row = row0 + rr;
                if (row < M) {
                    uint32_t w = *(uint32_t*)&sg[rr * SPH + f * 2];
                    *(uint32_t*)((char*)g_pk + ((size_t)row * 64 + f) * 16 + by4) = w;
                }
            }
        } else {
            // g_tp record 16B: [0,8)=t_k roles0..3, [8,16)=t_{k+1} roles0..3
#pragma unroll
            for (int i = 0; i < 32; i++) {
                int idx = tid + i * 256;
                int rr = idx >> 6, f = idx & 63;
                size_t k = (size_t)(row0 + rr);
                char* rec = (char*)g_tp + (k * 64 + f) * 16;
                uint32_t lo = *(uint32_t*)&sg[rr * SPH + f * 2];
                *(uint32_t*)(rec + by4) = lo;
                if (rr < 127) {
                    uint32_t hi = *(uint32_t*)&sg[(rr + 1) * SPH + f * 2];
                    *(uint32_t*)(rec + 8 + by4) = hi;
                }
            }
            // hi-half of previous tile's last record comes from our first row
            if (row0 > 0 && tid < 64) {
                uint32_t w0 = *(uint32_t*)&sg[0 * SPH + tid * 2];
                *(uint32_t*)((char*)g_tp + ((size_t)(row0 - 1) * 64 + tid) * 16 + 8 + by4) = w0;
            }
        }
    }
}

// ---------------- single-block exclusive scan (device body) -------------------
__device__ void scan_body(int A) {
    __shared__ int sh[256];
    int tid = threadIdx.x;
    int chunk = (A + 255) >> 8;
    int base = tid * chunk;
    int sum = 0;
    for (int j = 0; j < chunk; j++) {
        int idx = base + j;
        if (idx < A) sum += g_cnt[idx];
    }
    sh[tid] = sum;
    __syncthreads();
    for (int off = 1; off < 256; off <<= 1) {
        int v = 0;
        if (tid >= off) v = sh[tid - off];
        __syncthreads();
        sh[tid] += v;
        __syncthreads();
    }
    int run = (tid == 0) ? 0 : sh[tid - 1];
    for (int j = 0; j < chunk; j++) {
        int idx = base + j;
        if (idx < A) {
            g_off[idx] = run;
            g_pos[idx] = run;
            run += g_cnt[idx];
        }
    }
    if (base < A && A <= base + chunk) g_off[A] = run;
}

// ---------------- merged layer kernel: 2 GEMM problems + sort-step aux CTAs ---
__global__ void __launch_bounds__(256, 2) layer_kernel(
    GP pa, GP pt, int nA2, int nT2,
    int aux, const int* __restrict__ src, const int* __restrict__ dst, int E, int A)
{
    int bid = blockIdx.x;
    const int nG = nA2 + nT2;
    if (bid < nG) {
        bool isA = bid < nA2;
        GP p = isA ? pa : pt;
        int lb = isA ? bid : bid - nA2;
        gemm_body(p, lb >> 1, lb & 1);
        return;
    }
    int abid = bid - nG;
    int tid = threadIdx.x;
    if (aux == 1) {
        for (int t = abid * 256 + tid; t < E; t += 128 * 256)
            atomicAdd(&g_cnt[src[t]], 1);
    } else if (aux == 2) {
        scan_body(A);
    } else if (aux == 3) {
        // scatter edge PAYLOAD into sorted order
        for (int t = abid * 256 + tid; t < E; t += 128 * 256) {
            int pp = atomicAdd(&g_pos[src[t]], 1);
            g_sep[pp] = g_ep[t];
            g_sdst[pp] = dst[t];
        }
    }
}

// ---------------- per-atom gather: sequential payload + 16B gathers -----------
__global__ __launch_bounds__(256) void gather_kernel(
    const uint4* __restrict__ TP,           // g_tp: [k][f] = {t_k, t_{k+1}} 8 halves
    const uint4* __restrict__ PK,           // g_pk: [row][f] = {actv[4], v0..v2} 8 halves
    const float4* __restrict__ SEP,         // sorted (d0,d1,d2,idxf)
    const int* __restrict__ SDST,           // sorted dst
    float* __restrict__ out_a, float* __restrict__ out_v, int A)
{
    int a = blockIdx.x;
    int f = threadIdx.x & 63;
    int b = threadIdx.x >> 6;
    int p0 = g_off[a];
    int p1 = g_off[a + 1];

    float av0 = 0.f, av1 = 0.f, av2 = 0.f, aa = 0.f;
#pragma unroll 2
    for (int p = p0; p < p1; ++p) {
        float4 ed = __ldg(&SEP[p]);
        int dd = __ldg(&SDST[p]);
        float d0 = ed.x, d1 = ed.y, d2 = ed.z;
        int k = (int)ed.w;
        float w = ed.w - (float)k;

        uint4 tv = __ldg(&TP[(size_t)k * 64 + f]);
        float2 t0a = __half22float2(*(__half2*)&tv.x);
        float2 t0b = __half22float2(*(__half2*)&tv.y);
        float2 t1a = __half22float2(*(__half2*)&tv.z);
        float2 t1b = __half22float2(*(__half2*)&tv.w);
        float q0 = fmaf(w, t1a.x - t0a.x, t0a.x);
        float q1 = fmaf(w, t1a.y - t0a.y, t0a.y);
        float q2 = fmaf(w, t1b.x - t0b.x, t0b.x);
        float q3 = fmaf(w, t1b.y - t0b.y, t0b.y);

        uint4 pk = __ldg(&PK[(size_t)(b * A + dd) * 64 + f]);
        __half2 pra = *(__half2*)&pk.x;
        __half2 prb = *(__half2*)&pk.y;
        q0 *= __low2float(pra);
        q1 *= __high2float(pra);
        q2 *= __low2float(prb);
        q3 *= __high2float(prb);

        float2 va = __half22float2(*(__half2*)&pk.z);
        float v2f = __low2float(*(__half2*)&pk.w);
        float v0 = va.x, v1 = va.y, v2 = v2f;
        float c0 = v1 * d2 - v2 * d1;
        float c1 = v2 * d0 - v0 * d2;
        float c2 = v0 * d1 - v1 * d0;
        av0 += v0 * q0 + c0 * q1 + d0 * q2;
        av1 += v1 * q0 + c1 * q1 + d1 * q2;
        av2 += v2 * q0 + c2 * q1 + d2 * q2;
        aa  += q3;
    }
    out_a[(size_t)(b * A + a) * 64 + f] = aa;
    float* OV = out_v + (size_t)((b * A + a) * 64 + f) * 3;
    OV[0] = av0;
    OV[1] = av1;
    OV[2] = av2;
}

// ---------------- launch ------------------------------------------------------
extern "C" void kernel_launch(void* const* d_in, const int* in_sizes, int n_in,
                              void* d_out, int out_size) {
    const float* x_a  = (const float*)d_in[0];
    const float* x_v  = (const float*)d_in[1];
    const float* r_ij = (const float*)d_in[2];
    const int*   src  = (const int*)d_in[3];
    const int*   dst  = (const int*)d_in[4];
    const float* dW1 = (const float*)d_in[5];
    const float* db1 = (const float*)d_in[6];
    const float* dW2 = (const float*)d_in[7];
    const float* db2 = (const float*)d_in[8];
    const float* dW3 = (const float*)d_in[9];
    const float* db3 = (const float*)d_in[10];
    const float* aW1 = (const float*)d_in[11];
    const float* ab1 = (const float*)d_in[12];
    const float* aW2 = (const float*)d_in[13];
    const float* ab2 = (const float*)d_in[14];
    const float* aW3 = (const float*)d_in[15];
    const float* ab3 = (const float*)d_in[16];

    const int E  = in_sizes[3];
    const int BA = in_sizes[0] / NFEAT;
    const int A  = BA / 4;                 // B = 4

    __half *te_h, *te_l, *xa_h, *xa_l;
    __half *t1h, *t1l, *t2h, *t2l, *a1h, *a1l, *a2h, *a2l;
    __half *wh, *tp, *pk;
    float4 *sep;
    int *sdst;
    cudaGetSymbolAddress((void**)&te_h, g_te_h);
    cudaGetSymbolAddress((void**)&te_l, g_te_l);
    cudaGetSymbolAddress((void**)&xa_h, g_xa_h);
    cudaGetSymbolAddress((void**)&xa_l, g_xa_l);
    cudaGetSymbolAddress((void**)&t1h, g_t1h);
    cudaGetSymbolAddress((void**)&t1l, g_t1l);
    cudaGetSymbolAddress((void**)&t2h, g_t2h);
    cudaGetSymbolAddress((void**)&t2l, g_t2l);
    cudaGetSymbolAddress((void**)&a1h, g_a1h);
    cudaGetSymbolAddress((void**)&a1l, g_a1l);
    cudaGetSymbolAddress((void**)&a2h, g_a2h);
    cudaGetSymbolAddress((void**)&a2l, g_a2l);
    cudaGetSymbolAddress((void**)&wh, g_wh);
    cudaGetSymbolAddress((void**)&tp, g_tp);
    cudaGetSymbolAddress((void**)&pk, g_pk);
    cudaGetSymbolAddress((void**)&sep, g_sep);
    cudaGetSymbolAddress((void**)&sdst, g_sdst);

    cudaFuncSetAttribute(layer_kernel, cudaFuncAttributeMaxDynamicSharedMemorySize, 3 * STAGE_SZ);

    // 1) prep
    const int S1 = (BA * 64) / 256;
    const int SE = (E + 255) / 256;
    const int prep_blocks = (NTAB * 64 / 256) + 2 * S1 + SE + 1152 + (A + 1 + 255) / 256;
    prep_kernel<<<prep_blocks, 256>>>(x_a, x_v, r_ij, dW1, dW2, dW3, aW1, aW2, aW3, BA, A, E);

    const int nA2 = 2 * ((BA + 127) / 128);
    const int nT2 = 2 * (NTAB / 128);

    // 2) layer 1 (K=64) + hist
    {
        GP pa = { xa_h, xa_l, 64, wh + 3 * SLOT, ab1, BA, 64, 1, 0, a1h, a1l };
        GP pt = { te_h, te_l, 64, wh + 0 * SLOT, db1, NTAB, 64, 1, 0, t1h, t1l };
        layer_kernel<<<nA2 + nT2 + 128, 256, 3 * STAGE_SZ>>>(pa, pt, nA2, nT2, 1, src, dst, E, A);
    }
    // 3) layer 2 (K=256) + scan
    {
        GP pa = { a1h, a1l, 256, wh + 4 * SLOT, ab2, BA, 256, 1, 0, a2h, a2l };
        GP pt = { t1h, t1l, 256, wh + 1 * SLOT, db2, NTAB, 256, 1, 0, t2h, t2l };
        layer_kernel<<<nA2 + nT2 + 1, 256, 3 * STAGE_SZ>>>(pa, pt, nA2, nT2, 2, src, dst, E, A);
    }
    // 4) layer 3 (K=256, no act) + payload scatter; staged epilogue -> g_pk / g_tp
    {
        GP pa = { a2h, a2l, 256, wh + 5 * SLOT, ab3, BA, 256, 0, 2, nullptr, nullptr };
        GP pt = { t2h, t2l, 256, wh + 2 * SLOT, db3, NTAB, 256, 0, 3, nullptr, nullptr };
        layer_kernel<<<nA2 + nT2 + 128, 256, 3 * STAGE_SZ>>>(pa, pt, nA2, nT2, 3, src, dst, E, A);
    }

    // 5) gather
    float* out_a = (float*)d_out;
    float* out_v = (float*)d_out + (size_t)BA * NFEAT;
    gather_kernel<<<A, 256>>>((const uint4*)tp, (const uint4*)pk,
                              (const float4*)sep, (const int*)sdst, out_a, out_v, A);
}

// round 11
// speedup vs baseline: 1.0840x; 1.0147x over previous
#include <cuda_runtime.h>
#include <cuda_fp16.h>
#include <cstdint>

#define NFEAT 64
#define NHID  256
#define EMAX  320000
#define AMAX  10000
#define BAMAX 40000
#define EPS_F 0.1f
#define COEF0 0.31415926535897931f   // pi / R0, R0 = 10
#define NTAB  4096
#define DMAX  10.0f
#define TSCALE ((float)NTAB / DMAX)
#define SLOT  (256 * 256)

// ---------------- scratch (device globals; no allocation allowed) ------------
__device__ __half g_te_h[(size_t)NTAB * 64];
__device__ __half g_te_l[(size_t)NTAB * 64];
__device__ __half g_xa_h[(size_t)BAMAX * 64];
__device__ __half g_xa_l[(size_t)BAMAX * 64];
__device__ __half g_t1h[(size_t)NTAB * NHID];
__device__ __half g_t1l[(size_t)NTAB * NHID];
__device__ __half g_t2h[(size_t)NTAB * NHID];
__device__ __half g_t2l[(size_t)NTAB * NHID];
__device__ __half g_a1h[(size_t)BAMAX * NHID];
__device__ __half g_a1l[(size_t)BAMAX * NHID];
__device__ __half g_a2h[(size_t)BAMAX * NHID];
__device__ __half g_a2l[(size_t)BAMAX * NHID];
__device__ __half g_tp[(size_t)NTAB * 64 * 8];    // paired table: [k][f] = {t_k[4], t_{k+1}[4]}
__device__ __half g_pk[(size_t)BAMAX * 64 * 8];   // packed row: [row][f] = {actv[4], v0,v1,v2,0}
__device__ float4 g_sep[EMAX];                    // sorted edge payload (d0,d1,d2,idxf)
__device__ int    g_sdst[EMAX];                   // sorted dst
__device__ __half g_wh[6 * SLOT];                 // transposed weight hi
__device__ int g_cnt[AMAX + 1];
__device__ int g_off[AMAX + 1];
__device__ int g_pos[AMAX];

// ---------------- PTX helpers -------------------------------------------------
__device__ __forceinline__ uint32_t smem_u32(const void* p) {
    uint32_t a;
    asm("{ .reg .u64 t; cvta.to.shared.u64 t, %1; cvt.u32.u64 %0, t; }" : "=r"(a) : "l"(p));
    return a;
}
#define CP16(saddr, gptr) \
    asm volatile("cp.async.cg.shared.global [%0], [%1], 16;" :: "r"(saddr), "l"(gptr) : "memory")
#define CP_COMMIT asm volatile("cp.async.commit_group;" ::: "memory")
#define CP_WAIT0 asm volatile("cp.async.wait_group 0;" ::: "memory")
#define CP_WAIT1 asm volatile("cp.async.wait_group 1;" ::: "memory")

__device__ __forceinline__ void ldsm_x4(uint32_t* r, uint32_t addr) {
    asm volatile("ldmatrix.sync.aligned.m8n8.x4.shared.b16 {%0,%1,%2,%3}, [%4];"
                 : "=r"(r[0]), "=r"(r[1]), "=r"(r[2]), "=r"(r[3]) : "r"(addr));
}
__device__ __forceinline__ void mma16816(float* c, const uint32_t* a, uint32_t b0, uint32_t b1) {
    asm volatile("mma.sync.aligned.m16n8k16.row.col.f32.f16.f16.f32 "
                 "{%0,%1,%2,%3}, {%4,%5,%6,%7}, {%8,%9}, {%0,%1,%2,%3};"
                 : "+f"(c[0]), "+f"(c[1]), "+f"(c[2]), "+f"(c[3])
                 : "r"(a[0]), "r"(a[1]), "r"(a[2]), "r"(a[3]), "r"(b0), "r"(b1));
}
__device__ __forceinline__ void split_h(float v, __half& h, __half& l) {
    h = __float2half_rn(v);
    l = __float2half_rn(v - __half2float(h));
}

// ---------------- prep: tencode + split(x_a) + wtrans + zero ------------------
__global__ void prep_kernel(
    const float* __restrict__ x_a,
    const float* __restrict__ dW1, const float* __restrict__ dW2, const float* __restrict__ dW3,
    const float* __restrict__ aW1, const float* __restrict__ aW2, const float* __restrict__ aW3,
    int BA, int A)
{
    const int tid = threadIdx.x;
    int bid = blockIdx.x;
    const int S0 = NTAB * 64 / 256;
    const int S1 = (BA * 64) / 256;

    if (bid < S0) {
        int t = bid * 256 + tid;
        int k = t >> 6, j = t & 63;
        float d = (float)k * (DMAX / (float)NTAB);
        int kk = j & 31;
        float ph = (float)(1 + (kk >> 1)) * COEF0 * d;
        float v = (j < 32) ? cosf(ph) : sinf(ph);
        __half h, l;
        split_h(v, h, l);
        g_te_h[t] = h; g_te_l[t] = l;
        return;
    }
    bid -= S0;
    if (bid < S1) {
        int t = bid * 256 + tid;
        __half h, l;
        split_h(x_a[t], h, l);
        g_xa_h[t] = h; g_xa_l[t] = l;
        return;
    }
    bid -= S1;
    if (bid < 1152) {
        const float* W; int K, slot;
        if      (bid < 64)  { W = dW1; K = 64;  slot = 0; }
        else if (bid < 320) { W = dW2; K = 256; slot = 1; bid -= 64; }
        else if (bid < 576) { W = dW3; K = 256; slot = 2; bid -= 320; }
        else if (bid < 640) { W = aW1; K = 64;  slot = 3; bid -= 576; }
        else if (bid < 896) { W = aW2; K = 256; slot = 4; bid -= 640; }
        else                { W = aW3; K = 256; slot = 5; bid -= 896; }
        int t = bid * 256 + tid;
        int n = t & 255, k = t >> 8;
        g_wh[(size_t)slot * SLOT + (size_t)n * K + k] =
            __float2half_rn(W[(size_t)k * 256 + n]);
        return;
    }
    bid -= 1152;
    int t = bid * 256 + tid;
    if (t <= A) g_cnt[t] = 0;
}

// ---------------- GEMM problem descriptor + body ------------------------------
// mode 0: fp16 hi/lo out; mode 2: actv -> g_pk role-words; mode 3: table -> g_tp pair
struct GP {
    const __half* Ahi; const __half* Alo; int lda;
    const __half* Bhi;
    const float* bias;
    int M, K, act, mode;
    __half* OHi; __half* OLo;
};

#define HBK 64
#define ROWB 144   // 64 halves (128B) + 16B pad
#define A_HI_OFF 0
#define A_LO_OFF 18432
#define B_HI_OFF 36864
#define STAGE_SZ 55296
#define SPH 136    // epilogue staging pitch in halves

__device__ __forceinline__ void gemm_body(const GP p, int bx, int by) {
    extern __shared__ char smem[];
    const uint32_t sbase = smem_u32(smem);
    const int tid = threadIdx.x;
    const int lane = tid & 31;
    const int wid = tid >> 5;
    const int warp_m = wid & 3;
    const int warp_n = wid >> 2;
    const int row0 = bx * 128;
    const int col0 = by * 128;

    const uint32_t aoff = (uint32_t)(warp_m * 32 + (lane & 15)) * ROWB + ((lane >> 4) << 4);
    const uint32_t boff = (uint32_t)(warp_n * 64 + (lane & 7) + ((lane >> 4) << 3)) * ROWB
                        + (((lane >> 3) & 1) << 4);

    float acc[2][8][4];
#pragma unroll
    for (int tm = 0; tm < 2; tm++)
#pragma unroll
        for (int tn = 0; tn < 8; tn++)
#pragma unroll
            for (int j = 0; j < 4; j++) acc[tm][tn][j] = 0.f;

    const int NC = p.K / HBK;
    const int M = p.M;
    const int lda = p.lda;
    const int K = p.K;

    auto load_stage = [&](int buf, int kb) {
        const uint32_t sb = sbase + buf * STAGE_SZ;
#pragma unroll
        for (int it = 0; it < 4; it++) {
            int idx = tid + it * 256;
            int r = idx >> 3, cs = idx & 7;
            uint32_t so = (uint32_t)r * ROWB + cs * 16;
            size_t ga = (size_t)min(row0 + r, M - 1) * lda + kb + cs * 8;
            CP16(sb + A_HI_OFF + so, p.Ahi + ga);
            CP16(sb + A_LO_OFF + so, p.Alo + ga);
            size_t gb = (size_t)(col0 + r) * K + kb + cs * 8;
            CP16(sb + B_HI_OFF + so, p.Bhi + gb);
        }
    };

    // 2-stage pipeline, HBK=64 (half the barriers of HBK=32)
    load_stage(0, 0);
    CP_COMMIT;
    if (NC > 1) { load_stage(1, HBK); CP_COMMIT; }

    for (int c = 0; c < NC; c++) {
        if (c + 1 < NC) { CP_WAIT1; } else { CP_WAIT0; }
        __syncthreads();
        const uint32_t sb = sbase + (c & 1) * STAGE_SZ;
        const uint32_t abase = sb + aoff;
        const uint32_t bbase = sb + B_HI_OFF + boff;
#pragma unroll
        for (int ks = 0; ks < 4; ks++) {
            uint32_t ah[2][4], al[2][4], bb[4][4];
            ldsm_x4(ah[0], abase + ks * 32);
            ldsm_x4(ah[1], abase + 16 * ROWB + ks * 32);
            ldsm_x4(al[0], abase + A_LO_OFF + ks * 32);
            ldsm_x4(al[1], abase + A_LO_OFF + 16 * ROWB + ks * 32);
#pragma unroll
            for (int tg = 0; tg < 4; tg++)
                ldsm_x4(bb[tg], bbase + tg * 16 * ROWB + ks * 32);
#pragma unroll
            for (int tm = 0; tm < 2; tm++)
#pragma unroll
                for (int tn = 0; tn < 8; tn++) {
                    uint32_t b0 = bb[tn >> 1][(tn & 1) * 2];
                    uint32_t b1 = bb[tn >> 1][(tn & 1) * 2 + 1];
                    mma16816(acc[tm][tn], ah[tm], b0, b1);
                    mma16816(acc[tm][tn], al[tm], b0, b1);
                }
        }
        if (c + 2 < NC) {
            __syncthreads();
            load_stage(c & 1, (c + 2) * HBK);
            CP_COMMIT;
        }
    }

    __half* sg = (__half*)smem;   // staging reuse (modes 2/3)
    if (p.mode != 0) __syncthreads();   // pipeline smem now safe to reuse

#pragma unroll
    for (int tm = 0; tm < 2; tm++)
#pragma unroll
        for (int tn = 0; tn < 8; tn++) {
            int rl = warp_m * 32 + tm * 16 + (lane >> 2);    // local row 0..127
            int col = warp_n * 64 + tn * 8 + 2 * (lane & 3); // local col 0..127
            int r0 = row0 + rl;
            int gcol = col0 + col;
            float b0 = __ldg(&p.bias[gcol]);
            float b1 = __ldg(&p.bias[gcol + 1]);
            float v0 = acc[tm][tn][0] + b0;
            float v1 = acc[tm][tn][1] + b1;
            float v2 = acc[tm][tn][2] + b0;
            float v3 = acc[tm][tn][3] + b1;
            if (p.act) {
                v0 = v0 / (1.f + __expf(-v0));
                v1 = v1 / (1.f + __expf(-v1));
                v2 = v2 / (1.f + __expf(-v2));
                v3 = v3 / (1.f + __expf(-v3));
            }
            if (p.mode == 0) {
                __half h0, l0, h1, l1;
                if (r0 < M) {
                    split_h(v0, h0, l0); split_h(v1, h1, l1);
                    *(__half2*)&p.OHi[(size_t)r0 * 256 + gcol] = __halves2half2(h0, h1);
                    *(__half2*)&p.OLo[(size_t)r0 * 256 + gcol] = __halves2half2(l0, l1);
                }
                if (r0 + 8 < M) {
                    split_h(v2, h0, l0); split_h(v3, h1, l1);
                    *(__half2*)&p.OHi[(size_t)(r0 + 8) * 256 + gcol] = __halves2half2(h0, h1);
                    *(__half2*)&p.OLo[(size_t)(r0 + 8) * 256 + gcol] = __halves2half2(l0, l1);
                }
            } else {
                // stage: per (row, f) a 4B word holding our 2 roles
                int f = col & 63;
                int rlo = (col >> 6) & 1;
                sg[rl * SPH + f * 2 + rlo]             = __float2half_rn(v0);
                sg[rl * SPH + (f + 1) * 2 + rlo]       = __float2half_rn(v1);
                sg[(rl + 8) * SPH + f * 2 + rlo]       = __float2half_rn(v2);
                sg[(rl + 8) * SPH + (f + 1) * 2 + rlo] = __float2half_rn(v3);
            }
        }

    if (p.mode >= 2) {
        __syncthreads();
        const int by4 = by * 4;    // byte offset of our role-pair word within record
        if (p.mode == 2) {
            // g_pk record 16B: [0,4)=roles01, [4,8)=roles23, [8,16)=xv
#pragma unroll
            for (int i = 0; i < 32; i++) {
                int idx = tid + i * 256;
                int rr = idx >> 6, f = idx & 63;
                int row = row0 + rr;
                if (row < M) {
                    uint32_t w = *(uint32_t*)&sg[rr * SPH + f * 2];
                    *(uint32_t*)((char*)g_pk + ((size_t)row * 64 + f) * 16 + by4) = w;
                }
            }
        } else {
            // g_tp record 16B: [0,8)=t_k roles0..3, [8,16)=t_{k+1} roles0..3
#pragma unroll
            for (int i = 0; i < 32; i++) {
                int idx = tid + i * 256;
                int rr = idx >> 6, f = idx & 63;
                size_t k = (size_t)(row0 + rr);
                char* rec = (char*)g_tp + (k * 64 + f) * 16;
                uint32_t lo = *(uint32_t*)&sg[rr * SPH + f * 2];
                *(uint32_t*)(rec + by4) = lo;
                if (rr < 127) {
                    uint32_t hi = *(uint32_t*)&sg[(rr + 1) * SPH + f * 2];
                    *(uint32_t*)(rec + 8 + by4) = hi;
                }
            }
            if (row0 > 0 && tid < 64) {
                uint32_t w0 = *(uint32_t*)&sg[0 * SPH + tid * 2];
                *(uint32_t*)((char*)g_tp + ((size_t)(row0 - 1) * 64 + tid) * 16 + 8 + by4) = w0;
            }
        }
    }
}

// ---------------- single-block exclusive scan (device body) -------------------
__device__ void scan_body(int A) {
    __shared__ int sh[256];
    int tid = threadIdx.x;
    int chunk = (A + 255) >> 8;
    int base = tid * chunk;
    int sum = 0;
    for (int j = 0; j < chunk; j++) {
        int idx = base + j;
        if (idx < A) sum += g_cnt[idx];
    }
    sh[tid] = sum;
    __syncthreads();
    for (int off = 1; off < 256; off <<= 1) {
        int v = 0;
        if (tid >= off) v = sh[tid - off];
        __syncthreads();
        sh[tid] += v;
        __syncthreads();
    }
    int run = (tid == 0) ? 0 : sh[tid - 1];
    for (int j = 0; j < chunk; j++) {
        int idx = base + j;
        if (idx < A) {
            g_off[idx] = run;
            g_pos[idx] = run;
            run += g_cnt[idx];
        }
    }
    if (base < A && A <= base + chunk) g_off[A] = run;
}

// ---------------- merged layer kernel: 2 GEMM problems + aux CTAs -------------
// aux 1 (layer1): 128 hist CTAs + 128 xv-pack CTAs
// aux 2 (layer2): 1 scan CTA
// aux 3 (layer3): 128 payload-scatter CTAs (recompute dir/idx inline from r_ij)
__global__ void __launch_bounds__(256, 2) layer_kernel(
    GP pa, GP pt, int nA2, int nT2,
    int aux, const int* __restrict__ src, const int* __restrict__ dst,
    const float* __restrict__ r_ij, const float* __restrict__ x_v,
    int E, int A, int BA)
{
    int bid = blockIdx.x;
    const int nG = nA2 + nT2;
    if (bid < nG) {
        bool isA = bid < nA2;
        GP p = isA ? pa : pt;
        int lb = isA ? bid : bid - nA2;
        gemm_body(p, lb >> 1, lb & 1);
        return;
    }
    int abid = bid - nG;
    int tid = threadIdx.x;
    if (aux == 1) {
        if (abid < 128) {
            for (int t = abid * 256 + tid; t < E; t += 128 * 256)
                atomicAdd(&g_cnt[src[t]], 1);
        } else {
            // xv pack into g_pk slots 4..7 (concurrent with GEMM)
            int a2 = abid - 128;
            int n = BA * 64;
            for (int t = a2 * 256 + tid; t < n; t += 128 * 256) {
                float v0 = x_v[(size_t)t * 3 + 0];
                float v1 = x_v[(size_t)t * 3 + 1];
                float v2 = x_v[(size_t)t * 3 + 2];
                __half2* d2 = (__half2*)&g_pk[(size_t)t * 8 + 4];
                d2[0] = __floats2half2_rn(v0, v1);
                d2[1] = __floats2half2_rn(v2, 0.f);
            }
        }
    } else if (aux == 2) {
        scan_body(A);
    } else if (aux == 3) {
        // payload scatter: compute (d0,d1,d2,idxf) inline, identical expr order
        for (int t = abid * 256 + tid; t < E; t += 128 * 256) {
            float rx = r_ij[(size_t)t * 3 + 0];
            float ry = r_ij[(size_t)t * 3 + 1];
            float rz = r_ij[(size_t)t * 3 + 2];
            float d2s = rx * rx + ry * ry + rz * rz;
            float d = sqrtf(d2s);
            float inv = rsqrtf(EPS_F + d2s);
            float idxf = d * TSCALE;
            if (idxf > (float)(NTAB - 1) - 1e-3f) idxf = (float)(NTAB - 1) - 1e-3f;
            int pp = atomicAdd(&g_pos[src[t]], 1);
            g_sep[pp] = make_float4(rx * inv, ry * inv, rz * inv, idxf);
            g_sdst[pp] = dst[t];
        }
    }
}

// ---------------- per-atom gather: sequential payload + 16B gathers -----------
__global__ __launch_bounds__(256) void gather_kernel(
    const uint4* __restrict__ TP,
    const uint4* __restrict__ PK,
    const float4* __restrict__ SEP,
    const int* __restrict__ SDST,
    float* __restrict__ out_a, float* __restrict__ out_v, int A)
{
    int a = blockIdx.x;
    int f = threadIdx.x & 63;
    int b = threadIdx.x >> 6;
    int p0 = g_off[a];
    int p1 = g_off[a + 1];

    float av0 = 0.f, av1 = 0.f, av2 = 0.f, aa = 0.f;
#pragma unroll 2
    for (int p = p0; p < p1; ++p) {
        float4 ed = __ldg(&SEP[p]);
        int dd = __ldg(&SDST[p]);
        float d0 = ed.x, d1 = ed.y, d2 = ed.z;
        int k = (int)ed.w;
        float w = ed.w - (float)k;

        uint4 tv = __ldg(&TP[(size_t)k * 64 + f]);
        float2 t0a = __half22float2(*(__half2*)&tv.x);
        float2 t0b = __half22float2(*(__half2*)&tv.y);
        float2 t1a = __half22float2(*(__half2*)&tv.z);
        float2 t1b = __half22float2(*(__half2*)&tv.w);
        float q0 = fmaf(w, t1a.x - t0a.x, t0a.x);
        float q1 = fmaf(w, t1a.y - t0a.y, t0a.y);
        float q2 = fmaf(w, t1b.x - t0b.x, t0b.x);
        float q3 = fmaf(w, t1b.y - t0b.y, t0b.y);

        uint4 pk = __ldg(&PK[(size_t)(b * A + dd) * 64 + f]);
        __half2 pra = *(__half2*)&pk.x;
        __half2 prb = *(__half2*)&pk.y;
        q0 *= __low2float(pra);
        q1 *= __high2float(pra);
        q2 *= __low2float(prb);
        q3 *= __high2float(prb);

        float2 va = __half22float2(*(__half2*)&pk.z);
        float v2f = __low2float(*(__half2*)&pk.w);
        float v0 = va.x, v1 = va.y, v2 = v2f;
        float c0 = v1 * d2 - v2 * d1;
        float c1 = v2 * d0 - v0 * d2;
        float c2 = v0 * d1 - v1 * d0;
        av0 += v0 * q0 + c0 * q1 + d0 * q2;
        av1 += v1 * q0 + c1 * q1 + d1 * q2;
        av2 += v2 * q0 + c2 * q1 + d2 * q2;
        aa  += q3;
    }
    out_a[(size_t)(b * A + a) * 64 + f] = aa;
    float* OV = out_v + (size_t)((b * A + a) * 64 + f) * 3;
    OV[0] = av0;
    OV[1] = av1;
    OV[2] = av2;
}

// ---------------- launch ------------------------------------------------------
extern "C" void kernel_launch(void* const* d_in, const int* in_sizes, int n_in,
                              void* d_out, int out_size) {
    const float* x_a  = (const float*)d_in[0];
    const float* x_v  = (const float*)d_in[1];
    const float* r_ij = (const float*)d_in[2];
    const int*   src  = (const int*)d_in[3];
    const int*   dst  = (const int*)d_in[4];
    const float* dW1 = (const float*)d_in[5];
    const float* db1 = (const float*)d_in[6];
    const float* dW2 = (const float*)d_in[7];
    const float* db2 = (const float*)d_in[8];
    const float* dW3 = (const float*)d_in[9];
    const float* db3 = (const float*)d_in[10];
    const float* aW1 = (const float*)d_in[11];
    const float* ab1 = (const float*)d_in[12];
    const float* aW2 = (const float*)d_in[13];
    const float* ab2 = (const float*)d_in[14];
    const float* aW3 = (const float*)d_in[15];
    const float* ab3 = (const float*)d_in[16];

    const int E  = in_sizes[3];
    const int BA = in_sizes[0] / NFEAT;
    const int A  = BA / 4;                 // B = 4

    __half *te_h, *te_l, *xa_h, *xa_l;
    __half *t1h, *t1l, *t2h, *t2l, *a1h, *a1l, *a2h, *a2l;
    __half *wh, *tp, *pk;
    float4 *sep;
    int *sdst;
    cudaGetSymbolAddress((void**)&te_h, g_te_h);
    cudaGetSymbolAddress((void**)&te_l, g_te_l);
    cudaGetSymbolAddress((void**)&xa_h, g_xa_h);
    cudaGetSymbolAddress((void**)&xa_l, g_xa_l);
    cudaGetSymbolAddress((void**)&t1h, g_t1h);
    cudaGetSymbolAddress((void**)&t1l, g_t1l);
    cudaGetSymbolAddress((void**)&t2h, g_t2h);
    cudaGetSymbolAddress((void**)&t2l, g_t2l);
    cudaGetSymbolAddress((void**)&a1h, g_a1h);
    cudaGetSymbolAddress((void**)&a1l, g_a1l);
    cudaGetSymbolAddress((void**)&a2h, g_a2h);
    cudaGetSymbolAddress((void**)&a2l, g_a2l);
    cudaGetSymbolAddress((void**)&wh, g_wh);
    cudaGetSymbolAddress((void**)&tp, g_tp);
    cudaGetSymbolAddress((void**)&pk, g_pk);
    cudaGetSymbolAddress((void**)&sep, g_sep);
    cudaGetSymbolAddress((void**)&sdst, g_sdst);

    cudaFuncSetAttribute(layer_kernel, cudaFuncAttributeMaxDynamicSharedMemorySize, 2 * STAGE_SZ);

    // 1) prep: tencode + split(x_a) + wtrans x6 + zero_cnt
    const int S1 = (BA * 64) / 256;
    const int prep_blocks = (NTAB * 64 / 256) + S1 + 1152 + (A + 1 + 255) / 256;
    prep_kernel<<<prep_blocks, 256>>>(x_a, dW1, dW2, dW3, aW1, aW2, aW3, BA, A);

    const int nA2 = 2 * ((BA + 127) / 128);
    const int nT2 = 2 * (NTAB / 128);

    // 2) layer 1 (K=64) + hist + xv-pack
    {
        GP pa = { xa_h, xa_l, 64, wh + 3 * SLOT, ab1, BA, 64, 1, 0, a1h, a1l };
        GP pt = { te_h, te_l, 64, wh + 0 * SLOT, db1, NTAB, 64, 1, 0, t1h, t1l };
        layer_kernel<<<nA2 + nT2 + 256, 256, 2 * STAGE_SZ>>>(pa, pt, nA2, nT2, 1,
                                                             src, dst, r_ij, x_v, E, A, BA);
    }
    // 3) layer 2 (K=256) + scan
    {
        GP pa = { a1h, a1l, 256, wh + 4 * SLOT, ab2, BA, 256, 1, 0, a2h, a2l };
        GP pt = { t1h, t1l, 256, wh + 1 * SLOT, db2, NTAB, 256, 1, 0, t2h, t2l };
        layer_kernel<<<nA2 + nT2 + 1, 256, 2 * STAGE_SZ>>>(pa, pt, nA2, nT2, 2,
                                                           src, dst, r_ij, x_v, E, A, BA);
    }
    // 4) layer 3 (K=256, no act) + inline payload scatter; staged epilogue -> g_pk / g_tp
    {
        GP pa = { a2h, a2l, 256, wh + 5 * SLOT, ab3, BA, 256, 0, 2, nullptr, nullptr };
        GP pt = { t2h, t2l, 256, wh + 2 * SLOT, db3, NTAB, 256, 0, 3, nullptr, nullptr };
        layer_kernel<<<nA2 + nT2 + 128, 256, 2 * STAGE_SZ>>>(pa, pt, nA2, nT2, 3,
                                                             src, dst, r_ij, x_v, E, A, BA);
    }

    // 5) gather
    float* out_a = (float*)d_out;
    float* out_v = (float*)d_out + (size_t)BA * NFEAT;
    gather_kernel<<<A, 256>>>((const uint4*)tp, (const uint4*)pk,
                              (const float4*)sep, (const int*)sdst, out_a, out_v, A);
}

// round 12
// speedup vs baseline: 1.0926x; 1.0080x over previous
#include <cuda_runtime.h>
#include <cuda_fp16.h>
#include <cstdint>

#define NFEAT 64
#define NHID  256
#define EMAX  320000
#define AMAX  10000
#define BAMAX 40000
#define EPS_F 0.1f
#define COEF0 0.31415926535897931f   // pi / R0, R0 = 10
#define NTAB  4096
#define DMAX  10.0f
#define TSCALE ((float)NTAB / DMAX)
#define SLOT  (256 * 256)

// ---------------- scratch (device globals; no allocation allowed) ------------
__device__ __half g_te_h[(size_t)NTAB * 64];
__device__ __half g_te_l[(size_t)NTAB * 64];
__device__ __half g_xa_h[(size_t)BAMAX * 64];
__device__ __half g_xa_l[(size_t)BAMAX * 64];
__device__ __half g_tp[(size_t)NTAB * 64 * 8];    // paired table records
__device__ __half g_pk[(size_t)BAMAX * 64 * 8];   // packed row records
__device__ float4 g_sep[EMAX];
__device__ int    g_sdst[EMAX];
__device__ __half g_wh[6 * SLOT];
__device__ int g_cnt[AMAX + 1];
__device__ int g_off[AMAX + 1];
__device__ int g_pos[AMAX];

// ---------------- PTX helpers -------------------------------------------------
__device__ __forceinline__ uint32_t smem_u32(const void* p) {
    uint32_t a;
    asm("{ .reg .u64 t; cvta.to.shared.u64 t, %1; cvt.u32.u64 %0, t; }" : "=r"(a) : "l"(p));
    return a;
}
#define CP16(saddr, gptr) \
    asm volatile("cp.async.cg.shared.global [%0], [%1], 16;" :: "r"(saddr), "l"(gptr) : "memory")
#define CP_COMMIT asm volatile("cp.async.commit_group;" ::: "memory")
#define CP_WAIT0 asm volatile("cp.async.wait_group 0;" ::: "memory")
#define CP_WAIT1 asm volatile("cp.async.wait_group 1;" ::: "memory")

__device__ __forceinline__ void ldsm_x4(uint32_t* r, uint32_t addr) {
    asm volatile("ldmatrix.sync.aligned.m8n8.x4.shared.b16 {%0,%1,%2,%3}, [%4];"
                 : "=r"(r[0]), "=r"(r[1]), "=r"(r[2]), "=r"(r[3]) : "r"(addr));
}
__device__ __forceinline__ void mma16816(float* c, const uint32_t* a, uint32_t b0, uint32_t b1) {
    asm volatile("mma.sync.aligned.m16n8k16.row.col.f32.f16.f16.f32 "
                 "{%0,%1,%2,%3}, {%4,%5,%6,%7}, {%8,%9}, {%0,%1,%2,%3};"
                 : "+f"(c[0]), "+f"(c[1]), "+f"(c[2]), "+f"(c[3])
                 : "r"(a[0]), "r"(a[1]), "r"(a[2]), "r"(a[3]), "r"(b0), "r"(b1));
}
__device__ __forceinline__ void split_h(float v, __half& h, __half& l) {
    h = __float2half_rn(v);
    l = __float2half_rn(v - __half2float(h));
}

// ---------------- zero + scan tiny kernels ------------------------------------
__global__ void zero_kernel(int A) {
    int t = blockIdx.x * blockDim.x + threadIdx.x;
    if (t <= A) g_cnt[t] = 0;
}

__global__ void scan_kernel(int A) {
    __shared__ int sh[256];
    int tid = threadIdx.x;
    int chunk = (A + 255) >> 8;
    int base = tid * chunk;
    int sum = 0;
    for (int j = 0; j < chunk; j++) {
        int idx = base + j;
        if (idx < A) sum += g_cnt[idx];
    }
    sh[tid] = sum;
    __syncthreads();
    for (int off = 1; off < 256; off <<= 1) {
        int v = 0;
        if (tid >= off) v = sh[tid - off];
        __syncthreads();
        sh[tid] += v;
        __syncthreads();
    }
    int run = (tid == 0) ? 0 : sh[tid - 1];
    for (int j = 0; j < chunk; j++) {
        int idx = base + j;
        if (idx < A) {
            g_off[idx] = run;
            g_pos[idx] = run;
            run += g_cnt[idx];
        }
    }
    if (base < A && A <= base + chunk) g_off[A] = run;
}

// ---------------- prep: tencode + split(x_a) + wtrans + hist aux --------------
__global__ void prep_kernel(
    const float* __restrict__ x_a,
    const float* __restrict__ dW1, const float* __restrict__ dW2, const float* __restrict__ dW3,
    const float* __restrict__ aW1, const float* __restrict__ aW2, const float* __restrict__ aW3,
    const int* __restrict__ src, int BA, int E)
{
    const int tid = threadIdx.x;
    int bid = blockIdx.x;
    const int S0 = NTAB * 64 / 256;
    const int S1 = (BA * 64) / 256;

    if (bid < S0) {
        int t = bid * 256 + tid;
        int k = t >> 6, j = t & 63;
        float d = (float)k * (DMAX / (float)NTAB);
        int kk = j & 31;
        float ph = (float)(1 + (kk >> 1)) * COEF0 * d;
        float v = (j < 32) ? cosf(ph) : sinf(ph);
        __half h, l;
        split_h(v, h, l);
        g_te_h[t] = h; g_te_l[t] = l;
        return;
    }
    bid -= S0;
    if (bid < S1) {
        int t = bid * 256 + tid;
        __half h, l;
        split_h(x_a[t], h, l);
        g_xa_h[t] = h; g_xa_l[t] = l;
        return;
    }
    bid -= S1;
    if (bid < 1152) {
        const float* W; int K, slot;
        if      (bid < 64)  { W = dW1; K = 64;  slot = 0; }
        else if (bid < 320) { W = dW2; K = 256; slot = 1; bid -= 64; }
        else if (bid < 576) { W = dW3; K = 256; slot = 2; bid -= 320; }
        else if (bid < 640) { W = aW1; K = 64;  slot = 3; bid -= 576; }
        else if (bid < 896) { W = aW2; K = 256; slot = 4; bid -= 640; }
        else                { W = aW3; K = 256; slot = 5; bid -= 896; }
        int t = bid * 256 + tid;
        int n = t & 255, k = t >> 8;
        g_wh[(size_t)slot * SLOT + (size_t)n * K + k] =
            __float2half_rn(W[(size_t)k * 256 + n]);
        return;
    }
    bid -= 1152;
    // hist aux (128 CTAs); g_cnt zeroed by zero_kernel (previous launch)
    for (int t = bid * 256 + tid; t < E; t += 128 * 256)
        atomicAdd(&g_cnt[src[t]], 1);
}

// ---------------- fused 3-layer MLP kernel ------------------------------------
// CTA = 32 rows, full 256-wide outputs kept in SMEM between layers.
// SMEM map (bytes):
//   XA_HI 0       XA_LO 17408   (layer1 out; later reused as record staging)
//   XB_HI 34816   XB_LO 52224   (A0 input staging pitch 144, then layer2 out)
//   BST0  69632   BST1  88064   (B stream double buffer, 18432 each)
#define XROWB 544
#define XA_HI 0
#define XB_HI 34816
#define LODELTA 17408
#define BST0  69632
#define BST1  88064
#define FSMEM 106496
#define BROWB 144

struct Chain {
    const __half* inh; const __half* inl;
    const __half* W1; const __half* W2; const __half* W3;
    const float* b1; const float* b2; const float* b3;
};

__global__ void __launch_bounds__(256, 2) fused_kernel(
    Chain ca, Chain ct, int nA, int nT,
    const int* __restrict__ src, const int* __restrict__ dst,
    const float* __restrict__ r_ij, const float* __restrict__ x_v,
    int E, int A, int BA)
{
    extern __shared__ char smem[];
    const int tid = threadIdx.x;
    int bid = blockIdx.x;

    if (bid >= nA + nT) {
        int abid = bid - (nA + nT);
        if (abid < 128) {
            // payload scatter (needs scan from previous launch)
            for (int t = abid * 256 + tid; t < E; t += 128 * 256) {
                float rx = r_ij[(size_t)t * 3 + 0];
                float ry = r_ij[(size_t)t * 3 + 1];
                float rz = r_ij[(size_t)t * 3 + 2];
                float d2s = rx * rx + ry * ry + rz * rz;
                float d = sqrtf(d2s);
                float inv = rsqrtf(EPS_F + d2s);
                float idxf = d * TSCALE;
                if (idxf > (float)(NTAB - 1) - 1e-3f) idxf = (float)(NTAB - 1) - 1e-3f;
                int pp = atomicAdd(&g_pos[src[t]], 1);
                g_sep[pp] = make_float4(rx * inv, ry * inv, rz * inv, idxf);
                g_sdst[pp] = dst[t];
            }
        } else {
            // xv pack into g_pk bytes [8,16)
            int a2 = abid - 128;
            int n = BA * 64;
            for (int t = a2 * 256 + tid; t < n; t += 128 * 256) {
                float v0 = x_v[(size_t)t * 3 + 0];
                float v1 = x_v[(size_t)t * 3 + 1];
                float v2 = x_v[(size_t)t * 3 + 2];
                __half2* d2 = (__half2*)&g_pk[(size_t)t * 8 + 4];
                d2[0] = __floats2half2_rn(v0, v1);
                d2[1] = __floats2half2_rn(v2, 0.f);
            }
        }
        return;
    }

    const bool isA = bid < nA;
    const Chain C = isA ? ca : ct;
    const int row0 = (isA ? bid : bid - nA) * 32;

    const uint32_t sbase = smem_u32(smem);
    const int lane = tid & 31;
    const int wid = tid >> 5;
    const int warp_m = wid & 1;
    const int warp_n = wid >> 1;

    const uint32_t arow = (uint32_t)(warp_m * 16 + (lane & 15));
    const uint32_t asub = (uint32_t)((lane >> 4) << 4);
    const uint32_t boff = (uint32_t)(warp_n * 32 + (lane & 7) + ((lane >> 4) << 3)) * BROWB
                        + (((lane >> 3) & 1) << 4);

    const __half* Ws[3] = { C.W1, C.W2, C.W3 };
    const float* Bs[3] = { C.b1, C.b2, C.b3 };

    // A0 input staging (hi/lo, pitch 144) into XB region
    {
        int r = tid >> 3, cs = tid & 7;
        size_t ga = (size_t)(row0 + r) * 64 + cs * 8;
        uint32_t so = (uint32_t)r * BROWB + cs * 16;
        CP16(sbase + XB_HI + so, C.inh + ga);
        CP16(sbase + XB_HI + LODELTA + so, C.inl + ga);
    }

    auto load_B = [&](int slot, int s) {
        int L, n0, kb, K;
        if (s < 2)       { L = 0; n0 = s * 128;              kb = 0;               K = 64; }
        else if (s < 10) { L = 1; n0 = ((s - 2) >> 2) * 128; kb = ((s - 2) & 3) * 64;  K = 256; }
        else             { L = 2; n0 = ((s - 10) >> 2) * 128; kb = ((s - 10) & 3) * 64; K = 256; }
        const __half* W = Ws[L];
        uint32_t sb = sbase + (slot ? BST1 : BST0);
#pragma unroll
        for (int it = 0; it < 4; it++) {
            int idx = tid + it * 256;
            int r = idx >> 3, cs = idx & 7;
            CP16(sb + (uint32_t)r * BROWB + cs * 16,
                 W + (size_t)(n0 + r) * K + kb + cs * 8);
        }
    };

    load_B(0, 0); CP_COMMIT;   // group: A0 + B step0
    load_B(1, 1); CP_COMMIT;

    float acc[4][4];

    for (int s = 0; s < 18; s++) {
        int L, cb, c, last;
        if (s < 2)       { L = 0; cb = s;             c = 0;            last = 1; }
        else if (s < 10) { L = 1; cb = (s - 2) >> 2;  c = (s - 2) & 3;  last = (c == 3); }
        else             { L = 2; cb = (s - 10) >> 2; c = (s - 10) & 3; last = (c == 3); }

        if (s + 1 < 18) { CP_WAIT1; } else { CP_WAIT0; }
        __syncthreads();

        if (c == 0) {
#pragma unroll
            for (int tn = 0; tn < 4; tn++)
#pragma unroll
                for (int j = 0; j < 4; j++) acc[tn][j] = 0.f;
        }

        uint32_t ab;
        if (L == 0) ab = sbase + XB_HI + arow * BROWB + asub;
        else {
            uint32_t xh = (L == 1) ? XA_HI : XB_HI;
            ab = sbase + xh + arow * XROWB + asub + c * 128;
        }
        const uint32_t albase = ab + LODELTA;
        const uint32_t bbb = sbase + ((s & 1) ? BST1 : BST0) + boff;

#pragma unroll
        for (int ks = 0; ks < 4; ks++) {
            uint32_t ah[4], al[4], bb[2][4];
            ldsm_x4(ah, ab + ks * 32);
            ldsm_x4(al, albase + ks * 32);
            ldsm_x4(bb[0], bbb + ks * 32);
            ldsm_x4(bb[1], bbb + 16 * BROWB + ks * 32);
#pragma unroll
            for (int tn = 0; tn < 4; tn++) {
                uint32_t b0 = bb[tn >> 1][(tn & 1) * 2];
                uint32_t b1 = bb[tn >> 1][(tn & 1) * 2 + 1];
                mma16816(acc[tn], ah, b0, b1);
                mma16816(acc[tn], al, b0, b1);
            }
        }

        if (last) {
            const int act = (L < 2);
#pragma unroll
            for (int tn = 0; tn < 4; tn++) {
                int col = warp_n * 32 + tn * 8 + 2 * (lane & 3);
                int gcol = cb * 128 + col;
                int r0 = warp_m * 16 + (lane >> 2);
                float b0 = __ldg(&Bs[L][gcol]);
                float b1 = __ldg(&Bs[L][gcol + 1]);
                float v0 = acc[tn][0] + b0;
                float v1 = acc[tn][1] + b1;
                float v2 = acc[tn][2] + b0;
                float v3 = acc[tn][3] + b1;
                if (act) {
                    v0 = v0 / (1.f + __expf(-v0));
                    v1 = v1 / (1.f + __expf(-v1));
                    v2 = v2 / (1.f + __expf(-v2));
                    v3 = v3 / (1.f + __expf(-v3));
                }
                if (L < 2) {
                    const uint32_t xh = (L == 0) ? XA_HI : XB_HI;
                    char* base = smem + xh;
                    __half h0, l0, h1, l1;
                    split_h(v0, h0, l0); split_h(v1, h1, l1);
                    *(__half2*)(base + (size_t)r0 * XROWB + gcol * 2) = __halves2half2(h0, h1);
                    *(__half2*)(base + LODELTA + (size_t)r0 * XROWB + gcol * 2) = __halves2half2(l0, l1);
                    split_h(v2, h0, l0); split_h(v3, h1, l1);
                    *(__half2*)(base + (size_t)(r0 + 8) * XROWB + gcol * 2) = __halves2half2(h0, h1);
                    *(__half2*)(base + LODELTA + (size_t)(r0 + 8) * XROWB + gcol * 2) = __halves2half2(l0, l1);
                } else {
                    // stage record halves in XA region: [row][f][role], pitch 260 halves
                    __half* sg = (__half*)smem;
                    int f = gcol & 63, role = gcol >> 6;
                    sg[r0 * 260 + f * 4 + role]           = __float2half_rn(v0);
                    sg[r0 * 260 + (f + 1) * 4 + role]     = __float2half_rn(v1);
                    sg[(r0 + 8) * 260 + f * 4 + role]     = __float2half_rn(v2);
                    sg[(r0 + 8) * 260 + (f + 1) * 4 + role] = __float2half_rn(v3);
                }
            }
        }

        if (s + 2 < 18) {
            __syncthreads();
            load_B(s & 1, s + 2);
            CP_COMMIT;
        }
    }

    // final record writes (full 8B role-words per record)
    __syncthreads();
    __half* sg = (__half*)smem;
    if (isA) {
#pragma unroll
        for (int i = 0; i < 8; i++) {
            int idx = tid + i * 256;
            int rr = idx >> 6, f = idx & 63;
            uint2 w = *(uint2*)&sg[rr * 260 + f * 4];
            *(uint2*)((char*)g_pk + ((size_t)(row0 + rr) * 64 + f) * 16) = w;
        }
    } else {
#pragma unroll
        for (int i = 0; i < 8; i++) {
            int idx = tid + i * 256;
            int rr = idx >> 6, f = idx & 63;
            char* rec = (char*)g_tp + (((size_t)(row0 + rr)) * 64 + f) * 16;
            uint2 lo = *(uint2*)&sg[rr * 260 + f * 4];
            *(uint2*)rec = lo;
            if (rr < 31) {
                uint2 hi = *(uint2*)&sg[(rr + 1) * 260 + f * 4];
                *(uint2*)(rec + 8) = hi;
            }
        }
        if (row0 > 0 && tid < 64) {
            uint2 w0 = *(uint2*)&sg[0 * 260 + tid * 4];
            *(uint2*)((char*)g_tp + ((size_t)(row0 - 1) * 64 + tid) * 16 + 8) = w0;
        }
    }
}

// ---------------- per-atom gather (unchanged) ---------------------------------
__global__ __launch_bounds__(256) void gather_kernel(
    const uint4* __restrict__ TP,
    const uint4* __restrict__ PK,
    const float4* __restrict__ SEP,
    const int* __restrict__ SDST,
    float* __restrict__ out_a, float* __restrict__ out_v, int A)
{
    int a = blockIdx.x;
    int f = threadIdx.x & 63;
    int b = threadIdx.x >> 6;
    int p0 = g_off[a];
    int p1 = g_off[a + 1];

    float av0 = 0.f, av1 = 0.f, av2 = 0.f, aa = 0.f;
#pragma unroll 2
    for (int p = p0; p < p1; ++p) {
        float4 ed = __ldg(&SEP[p]);
        int dd = __ldg(&SDST[p]);
        float d0 = ed.x, d1 = ed.y, d2 = ed.z;
        int k = (int)ed.w;
        float w = ed.w - (float)k;

        uint4 tv = __ldg(&TP[(size_t)k * 64 + f]);
        float2 t0a = __half22float2(*(__half2*)&tv.x);
        float2 t0b = __half22float2(*(__half2*)&tv.y);
        float2 t1a = __half22float2(*(__half2*)&tv.z);
        float2 t1b = __half22float2(*(__half2*)&tv.w);
        float q0 = fmaf(w, t1a.x - t0a.x, t0a.x);
        float q1 = fmaf(w, t1a.y - t0a.y, t0a.y);
        float q2 = fmaf(w, t1b.x - t0b.x, t0b.x);
        float q3 = fmaf(w, t1b.y - t0b.y, t0b.y);

        uint4 pk = __ldg(&PK[(size_t)(b * A + dd) * 64 + f]);
        __half2 pra = *(__half2*)&pk.x;
        __half2 prb = *(__half2*)&pk.y;
        q0 *= __low2float(pra);
        q1 *= __high2float(pra);
        q2 *= __low2float(prb);
        q3 *= __high2float(prb);

        float2 va = __half22float2(*(__half2*)&pk.z);
        float v2f = __low2float(*(__half2*)&pk.w);
        float v0 = va.x, v1 = va.y, v2 = v2f;
        float c0 = v1 * d2 - v2 * d1;
        float c1 = v2 * d0 - v0 * d2;
        float c2 = v0 * d1 - v1 * d0;
        av0 += v0 * q0 + c0 * q1 + d0 * q2;
        av1 += v1 * q0 + c1 * q1 + d1 * q2;
        av2 += v2 * q0 + c2 * q1 + d2 * q2;
        aa  += q3;
    }
    out_a[(size_t)(b * A + a) * 64 + f] = aa;
    float* OV = out_v + (size_t)((b * A + a) * 64 + f) * 3;
    OV[0] = av0;
    OV[1] = av1;
    OV[2] = av2;
}

// ---------------- launch ------------------------------------------------------
extern "C" void kernel_launch(void* const* d_in, const int* in_sizes, int n_in,
                              void* d_out, int out_size) {
    const float* x_a  = (const float*)d_in[0];
    const float* x_v  = (const float*)d_in[1];
    const float* r_ij = (const float*)d_in[2];
    const int*   src  = (const int*)d_in[3];
    const int*   dst  = (const int*)d_in[4];
    const float* dW1 = (const float*)d_in[5];
    const float* db1 = (const float*)d_in[6];
    const float* dW2 = (const float*)d_in[7];
    const float* db2 = (const float*)d_in[8];
    const float* dW3 = (const float*)d_in[9];
    const float* db3 = (const float*)d_in[10];
    const float* aW1 = (const float*)d_in[11];
    const float* ab1 = (const float*)d_in[12];
    const float* aW2 = (const float*)d_in[13];
    const float* ab2 = (const float*)d_in[14];
    const float* aW3 = (const float*)d_in[15];
    const float* ab3 = (const float*)d_in[16];

    const int E  = in_sizes[3];
    const int BA = in_sizes[0] / NFEAT;
    const int A  = BA / 4;                 // B = 4

    __half *te_h, *te_l, *xa_h, *xa_l, *wh, *tp, *pk;
    float4 *sep;
    int *sdst;
    cudaGetSymbolAddress((void**)&te_h, g_te_h);
    cudaGetSymbolAddress((void**)&te_l, g_te_l);
    cudaGetSymbolAddress((void**)&xa_h, g_xa_h);
    cudaGetSymbolAddress((void**)&xa_l, g_xa_l);
    cudaGetSymbolAddress((void**)&wh, g_wh);
    cudaGetSymbolAddress((void**)&tp, g_tp);
    cudaGetSymbolAddress((void**)&pk, g_pk);
    cudaGetSymbolAddress((void**)&sep, g_sep);
    cudaGetSymbolAddress((void**)&sdst, g_sdst);

    cudaFuncSetAttribute(fused_kernel, cudaFuncAttributeMaxDynamicSharedMemorySize, FSMEM);

    // 1) zero histogram
    zero_kernel<<<(A + 1 + 255) / 256, 256>>>(A);

    // 2) prep (tencode + split + wtrans) + hist aux
    const int S1 = (BA * 64) / 256;
    prep_kernel<<<(NTAB * 64 / 256) + S1 + 1152 + 128, 256>>>(
        x_a, dW1, dW2, dW3, aW1, aW2, aW3, src, BA, E);

    // 3) scan
    scan_kernel<<<1, 256>>>(A);

    // 4) fused 3-layer MLP (both chains) + scatter aux + xv-pack aux
    const int nA = BA / 32;
    const int nT = NTAB / 32;
    Chain ca = { xa_h, xa_l, wh + 3 * SLOT, wh + 4 * SLOT, wh + 5 * SLOT, ab1, ab2, ab3 };
    Chain ct = { te_h, te_l, wh + 0 * SLOT, wh + 1 * SLOT, wh + 2 * SLOT, db1, db2, db3 };
    fused_kernel<<<nA + nT + 256, 256, FSMEM>>>(ca, ct, nA, nT,
                                                src, dst, r_ij, x_v, E, A, BA);

    // 5) gather
    float* out_a = (float*)d_out;
    float* out_v = (float*)d_out + (size_t)BA * NFEAT;
    gather_kernel<<<A, 256>>>((const uint4*)tp, (const uint4*)pk,
                              (const float4*)sep, (const int*)sdst, out_a, out_v, A);
}

// round 13
// speedup vs baseline: 1.1287x; 1.0330x over previous
#include <cuda_runtime.h>
#include <cuda_fp16.h>
#include <cstdint>

#define NFEAT 64
#define NHID  256
#define EMAX  320000
#define AMAX  10000
#define BAMAX 40000
#define EPS_F 0.1f
#define COEF0 0.31415926535897931f   // pi / R0, R0 = 10
#define NTAB  4096
#define DMAX  10.0f
#define TSCALE ((float)NTAB / DMAX)
#define SLOT  (256 * 256)

// ---------------- scratch (device globals; no allocation allowed) ------------
__device__ __half g_te_h[(size_t)NTAB * 64];
__device__ __half g_te_l[(size_t)NTAB * 64];
__device__ __half g_xa_h[(size_t)BAMAX * 64];
__device__ __half g_xa_l[(size_t)BAMAX * 64];
__device__ __half g_tp[(size_t)NTAB * 64 * 8];    // paired table records
__device__ __half g_pk[(size_t)BAMAX * 64 * 8];   // packed row records
__device__ float4 g_sep[EMAX];
__device__ int    g_sdst[EMAX];
__device__ __half g_wh[6 * SLOT];
__device__ int g_cnt[AMAX + 1];
__device__ int g_off[AMAX + 1];
__device__ int g_pos[AMAX];

// ---------------- PTX helpers -------------------------------------------------
__device__ __forceinline__ uint32_t smem_u32(const void* p) {
    uint32_t a;
    asm("{ .reg .u64 t; cvta.to.shared.u64 t, %1; cvt.u32.u64 %0, t; }" : "=r"(a) : "l"(p));
    return a;
}
#define CP16(saddr, gptr) \
    asm volatile("cp.async.cg.shared.global [%0], [%1], 16;" :: "r"(saddr), "l"(gptr) : "memory")
#define CP_COMMIT asm volatile("cp.async.commit_group;" ::: "memory")
#define CP_WAIT0 asm volatile("cp.async.wait_group 0;" ::: "memory")
#define CP_WAIT1 asm volatile("cp.async.wait_group 1;" ::: "memory")

__device__ __forceinline__ void ldsm_x4(uint32_t* r, uint32_t addr) {
    asm volatile("ldmatrix.sync.aligned.m8n8.x4.shared.b16 {%0,%1,%2,%3}, [%4];"
                 : "=r"(r[0]), "=r"(r[1]), "=r"(r[2]), "=r"(r[3]) : "r"(addr));
}
__device__ __forceinline__ void mma16816(float* c, const uint32_t* a, uint32_t b0, uint32_t b1) {
    asm volatile("mma.sync.aligned.m16n8k16.row.col.f32.f16.f16.f32 "
                 "{%0,%1,%2,%3}, {%4,%5,%6,%7}, {%8,%9}, {%0,%1,%2,%3};"
                 : "+f"(c[0]), "+f"(c[1]), "+f"(c[2]), "+f"(c[3])
                 : "r"(a[0]), "r"(a[1]), "r"(a[2]), "r"(a[3]), "r"(b0), "r"(b1));
}
__device__ __forceinline__ void split_h(float v, __half& h, __half& l) {
    h = __float2half_rn(v);
    l = __float2half_rn(v - __half2float(h));
}

// ---------------- zero + scan tiny kernels ------------------------------------
__global__ void zero_kernel(int A) {
    int t = blockIdx.x * blockDim.x + threadIdx.x;
    if (t <= A) g_cnt[t] = 0;
}

__global__ void scan_kernel(int A) {
    __shared__ int sh[256];
    int tid = threadIdx.x;
    int chunk = (A + 255) >> 8;
    int base = tid * chunk;
    int sum = 0;
    for (int j = 0; j < chunk; j++) {
        int idx = base + j;
        if (idx < A) sum += g_cnt[idx];
    }
    sh[tid] = sum;
    __syncthreads();
    for (int off = 1; off < 256; off <<= 1) {
        int v = 0;
        if (tid >= off) v = sh[tid - off];
        __syncthreads();
        sh[tid] += v;
        __syncthreads();
    }
    int run = (tid == 0) ? 0 : sh[tid - 1];
    for (int j = 0; j < chunk; j++) {
        int idx = base + j;
        if (idx < A) {
            g_off[idx] = run;
            g_pos[idx] = run;
            run += g_cnt[idx];
        }
    }
    if (base < A && A <= base + chunk) g_off[A] = run;
}

// ---------------- prep: tencode + split(x_a) + wtrans + hist aux --------------
__global__ void prep_kernel(
    const float* __restrict__ x_a,
    const float* __restrict__ dW1, const float* __restrict__ dW2, const float* __restrict__ dW3,
    const float* __restrict__ aW1, const float* __restrict__ aW2, const float* __restrict__ aW3,
    const int* __restrict__ src, int BA, int E)
{
    const int tid = threadIdx.x;
    int bid = blockIdx.x;
    const int S0 = NTAB * 64 / 256;
    const int S1 = (BA * 64) / 256;

    if (bid < S0) {
        int t = bid * 256 + tid;
        int k = t >> 6, j = t & 63;
        float d = (float)k * (DMAX / (float)NTAB);
        int kk = j & 31;
        float ph = (float)(1 + (kk >> 1)) * COEF0 * d;
        float v = (j < 32) ? cosf(ph) : sinf(ph);
        __half h, l;
        split_h(v, h, l);
        g_te_h[t] = h; g_te_l[t] = l;
        return;
    }
    bid -= S0;
    if (bid < S1) {
        int t = bid * 256 + tid;
        __half h, l;
        split_h(x_a[t], h, l);
        g_xa_h[t] = h; g_xa_l[t] = l;
        return;
    }
    bid -= S1;
    if (bid < 1152) {
        const float* W; int K, slot;
        if      (bid < 64)  { W = dW1; K = 64;  slot = 0; }
        else if (bid < 320) { W = dW2; K = 256; slot = 1; bid -= 64; }
        else if (bid < 576) { W = dW3; K = 256; slot = 2; bid -= 320; }
        else if (bid < 640) { W = aW1; K = 64;  slot = 3; bid -= 576; }
        else if (bid < 896) { W = aW2; K = 256; slot = 4; bid -= 640; }
        else                { W = aW3; K = 256; slot = 5; bid -= 896; }
        int t = bid * 256 + tid;
        int n = t & 255, k = t >> 8;
        g_wh[(size_t)slot * SLOT + (size_t)n * K + k] =
            __float2half_rn(W[(size_t)k * 256 + n]);
        return;
    }
    bid -= 1152;
    for (int t = bid * 256 + tid; t < E; t += 128 * 256)
        atomicAdd(&g_cnt[src[t]], 1);
}

// ---------------- fused 3-layer MLP kernel ------------------------------------
// CTA = 64 rows, 512 threads, warp tile 16x64, full 256-wide output per step.
// SMEM map (bytes):
//   XA_HI 0       XA_LO 33792    (layer1 out, pitch 528; later record staging)
//   XB_HI 67584   XB_LO 101376   (A0 staging pitch 144; then layer2 out pitch 528)
//   BST0  135168  BST1  172032   (B stream double buffer, 36864 each)
#define XROWB 528
#define XA_HI 0
#define XB_HI 67584
#define LODELTA 33792
#define BST0  135168
#define BST1  172032
#define FSMEM 208896
#define BROWB 144
#define NSTEP 9

struct Chain {
    const __half* inh; const __half* inl;
    const __half* W1; const __half* W2; const __half* W3;
    const float* b1; const float* b2; const float* b3;
};

__global__ void __launch_bounds__(512, 1) fused_kernel(
    Chain ca, Chain ct, int nA, int nT,
    const int* __restrict__ src, const int* __restrict__ dst,
    const float* __restrict__ r_ij, const float* __restrict__ x_v,
    int E, int A, int BA)
{
    extern __shared__ char smem[];
    const int tid = threadIdx.x;
    int bid = blockIdx.x;

    if (bid >= nA + nT) {
        int abid = bid - (nA + nT);
        if (abid < 128) {
            // payload scatter
            for (int t = abid * 512 + tid; t < E; t += 128 * 512) {
                float rx = r_ij[(size_t)t * 3 + 0];
                float ry = r_ij[(size_t)t * 3 + 1];
                float rz = r_ij[(size_t)t * 3 + 2];
                float d2s = rx * rx + ry * ry + rz * rz;
                float d = sqrtf(d2s);
                float inv = rsqrtf(EPS_F + d2s);
                float idxf = d * TSCALE;
                if (idxf > (float)(NTAB - 1) - 1e-3f) idxf = (float)(NTAB - 1) - 1e-3f;
                int pp = atomicAdd(&g_pos[src[t]], 1);
                g_sep[pp] = make_float4(rx * inv, ry * inv, rz * inv, idxf);
                g_sdst[pp] = dst[t];
            }
        } else {
            // xv pack into g_pk bytes [8,16)
            int a2 = abid - 128;
            int n = BA * 64;
            for (int t = a2 * 512 + tid; t < n; t += 128 * 512) {
                float v0 = x_v[(size_t)t * 3 + 0];
                float v1 = x_v[(size_t)t * 3 + 1];
                float v2 = x_v[(size_t)t * 3 + 2];
                __half2* d2 = (__half2*)&g_pk[(size_t)t * 8 + 4];
                d2[0] = __floats2half2_rn(v0, v1);
                d2[1] = __floats2half2_rn(v2, 0.f);
            }
        }
        return;
    }

    const bool isA = bid < nA;
    const Chain C = isA ? ca : ct;
    const int row0 = (isA ? bid : bid - nA) * 64;

    const uint32_t sbase = smem_u32(smem);
    const int lane = tid & 31;
    const int wid = tid >> 5;
    const int warp_m = wid & 3;     // 4 x 16 rows
    const int warp_n = wid >> 2;    // 4 x 64 cols

    const uint32_t arow = (uint32_t)(warp_m * 16 + (lane & 15));
    const uint32_t asub = (uint32_t)((lane >> 4) << 4);
    const uint32_t boff = (uint32_t)(warp_n * 64 + (lane & 7) + ((lane >> 4) << 3)) * BROWB
                        + (((lane >> 3) & 1) << 4);

    const __half* Ws[3] = { C.W1, C.W2, C.W3 };
    const float* Bs[3] = { C.b1, C.b2, C.b3 };

    // A0 input staging (hi/lo, pitch 144) into XB region: 64 rows x 8 chunks = 512
    {
        int r = tid >> 3, cs = tid & 7;
        size_t ga = (size_t)(row0 + r) * 64 + cs * 8;
        uint32_t so = (uint32_t)r * BROWB + cs * 16;
        CP16(sbase + XB_HI + so, C.inh + ga);
        CP16(sbase + XB_HI + LODELTA + so, C.inl + ga);
    }

    // B stream: step s covers full 256 output rows, one 64-wide K chunk
    auto load_B = [&](int slot, int s) {
        int L, kb, K;
        if (s == 0)     { L = 0; kb = 0;            K = 64; }
        else if (s < 5) { L = 1; kb = (s - 1) * 64; K = 256; }
        else            { L = 2; kb = (s - 5) * 64; K = 256; }
        const __half* W = Ws[L];
        uint32_t sb = sbase + (slot ? BST1 : BST0);
#pragma unroll
        for (int it = 0; it < 4; it++) {
            int idx = tid + it * 512;
            int r = idx >> 3, cs = idx & 7;
            CP16(sb + (uint32_t)r * BROWB + cs * 16,
                 W + (size_t)r * K + kb + cs * 8);
        }
    };

    load_B(0, 0); CP_COMMIT;   // group: A0 + B step0
    load_B(1, 1); CP_COMMIT;

    float acc[8][4];

    for (int s = 0; s < NSTEP; s++) {
        int L, c, last;
        if (s == 0)     { L = 0; c = 0;     last = 1; }
        else if (s < 5) { L = 1; c = s - 1; last = (c == 3); }
        else            { L = 2; c = s - 5; last = (c == 3); }

        if (s + 1 < NSTEP) { CP_WAIT1; } else { CP_WAIT0; }
        __syncthreads();

        if (c == 0) {
#pragma unroll
            for (int tn = 0; tn < 8; tn++)
#pragma unroll
                for (int j = 0; j < 4; j++) acc[tn][j] = 0.f;
        }

        uint32_t ab;
        if (L == 0) ab = sbase + XB_HI + arow * BROWB + asub;
        else {
            uint32_t xh = (L == 1) ? XA_HI : XB_HI;
            ab = sbase + xh + arow * XROWB + asub + c * 128;
        }
        const uint32_t albase = ab + LODELTA;
        const uint32_t bbb = sbase + ((s & 1) ? BST1 : BST0) + boff;

#pragma unroll
        for (int ks = 0; ks < 4; ks++) {
            uint32_t ah[4], al[4], bb[4][4];
            ldsm_x4(ah, ab + ks * 32);
            ldsm_x4(al, albase + ks * 32);
#pragma unroll
            for (int tg = 0; tg < 4; tg++)
                ldsm_x4(bb[tg], bbb + tg * 16 * BROWB + ks * 32);
#pragma unroll
            for (int tn = 0; tn < 8; tn++) {
                uint32_t b0 = bb[tn >> 1][(tn & 1) * 2];
                uint32_t b1 = bb[tn >> 1][(tn & 1) * 2 + 1];
                mma16816(acc[tn], ah, b0, b1);
                mma16816(acc[tn], al, b0, b1);
            }
        }

        if (last) {
            const int act = (L < 2);
#pragma unroll
            for (int tn = 0; tn < 8; tn++) {
                int gcol = warp_n * 64 + tn * 8 + 2 * (lane & 3);
                int r0 = warp_m * 16 + (lane >> 2);
                float b0 = __ldg(&Bs[L][gcol]);
                float b1 = __ldg(&Bs[L][gcol + 1]);
                float v0 = acc[tn][0] + b0;
                float v1 = acc[tn][1] + b1;
                float v2 = acc[tn][2] + b0;
                float v3 = acc[tn][3] + b1;
                if (act) {
                    v0 = v0 / (1.f + __expf(-v0));
                    v1 = v1 / (1.f + __expf(-v1));
                    v2 = v2 / (1.f + __expf(-v2));
                    v3 = v3 / (1.f + __expf(-v3));
                }
                if (L < 2) {
                    const uint32_t xh = (L == 0) ? XA_HI : XB_HI;
                    char* base = smem + xh;
                    __half h0, l0, h1, l1;
                    split_h(v0, h0, l0); split_h(v1, h1, l1);
                    *(__half2*)(base + (size_t)r0 * XROWB + gcol * 2) = __halves2half2(h0, h1);
                    *(__half2*)(base + LODELTA + (size_t)r0 * XROWB + gcol * 2) = __halves2half2(l0, l1);
                    split_h(v2, h0, l0); split_h(v3, h1, l1);
                    *(__half2*)(base + (size_t)(r0 + 8) * XROWB + gcol * 2) = __halves2half2(h0, h1);
                    *(__half2*)(base + LODELTA + (size_t)(r0 + 8) * XROWB + gcol * 2) = __halves2half2(l0, l1);
                } else {
                    // stage record halves in XA region: [row][f][role], pitch 260 halves
                    __half* sg = (__half*)smem;
                    int f = gcol & 63, role = gcol >> 6;
                    sg[r0 * 260 + f * 4 + role]             = __float2half_rn(v0);
                    sg[r0 * 260 + (f + 1) * 4 + role]       = __float2half_rn(v1);
                    sg[(r0 + 8) * 260 + f * 4 + role]       = __float2half_rn(v2);
                    sg[(r0 + 8) * 260 + (f + 1) * 4 + role] = __float2half_rn(v3);
                }
            }
        }

        if (s + 2 < NSTEP) {
            __syncthreads();
            load_B(s & 1, s + 2);
            CP_COMMIT;
        }
    }

    // final record writes (full 8B role-words per record): 64*64 entries / 512 = 8
    __syncthreads();
    __half* sg = (__half*)smem;
    if (isA) {
#pragma unroll
        for (int i = 0; i < 8; i++) {
            int idx = tid + i * 512;
            int rr = idx >> 6, f = idx & 63;
            uint2 w = *(uint2*)&sg[rr * 260 + f * 4];
            *(uint2*)((char*)g_pk + ((size_t)(row0 + rr) * 64 + f) * 16) = w;
        }
    } else {
#pragma unroll
        for (int i = 0; i < 8; i++) {
            int idx = tid + i * 512;
            int rr = idx >> 6, f = idx & 63;
            char* rec = (char*)g_tp + (((size_t)(row0 + rr)) * 64 + f) * 16;
            uint2 lo = *(uint2*)&sg[rr * 260 + f * 4];
            *(uint2*)rec = lo;
            if (rr < 63) {
                uint2 hi = *(uint2*)&sg[(rr + 1) * 260 + f * 4];
                *(uint2*)(rec + 8) = hi;
            }
        }
        if (row0 > 0 && tid < 64) {
            uint2 w0 = *(uint2*)&sg[0 * 260 + tid * 4];
            *(uint2*)((char*)g_tp + ((size_t)(row0 - 1) * 64 + tid) * 16 + 8) = w0;
        }
    }
}

// ---------------- per-atom gather (unchanged) ---------------------------------
__global__ __launch_bounds__(256) void gather_kernel(
    const uint4* __restrict__ TP,
    const uint4* __restrict__ PK,
    const float4* __restrict__ SEP,
    const int* __restrict__ SDST,
    float* __restrict__ out_a, float* __restrict__ out_v, int A)
{
    int a = blockIdx.x;
    int f = threadIdx.x & 63;
    int b = threadIdx.x >> 6;
    int p0 = g_off[a];
    int p1 = g_off[a + 1];

    float av0 = 0.f, av1 = 0.f, av2 = 0.f, aa = 0.f;
#pragma unroll 2
    for (int p = p0; p < p1; ++p) {
        float4 ed = __ldg(&SEP[p]);
        int dd = __ldg(&SDST[p]);
        float d0 = ed.x, d1 = ed.y, d2 = ed.z;
        int k = (int)ed.w;
        float w = ed.w - (float)k;

        uint4 tv = __ldg(&TP[(size_t)k * 64 + f]);
        float2 t0a = __half22float2(*(__half2*)&tv.x);
        float2 t0b = __half22float2(*(__half2*)&tv.y);
        float2 t1a = __half22float2(*(__half2*)&tv.z);
        float2 t1b = __half22float2(*(__half2*)&tv.w);
        float q0 = fmaf(w, t1a.x - t0a.x, t0a.x);
        float q1 = fmaf(w, t1a.y - t0a.y, t0a.y);
        float q2 = fmaf(w, t1b.x - t0b.x, t0b.x);
        float q3 = fmaf(w, t1b.y - t0b.y, t0b.y);

        uint4 pk = __ldg(&PK[(size_t)(b * A + dd) * 64 + f]);
        __half2 pra = *(__half2*)&pk.x;
        __half2 prb = *(__half2*)&pk.y;
        q0 *= __low2float(pra);
        q1 *= __high2float(pra);
        q2 *= __low2float(prb);
        q3 *= __high2float(prb);

        float2 va = __half22float2(*(__half2*)&pk.z);
        float v2f = __low2float(*(__half2*)&pk.w);
        float v0 = va.x, v1 = va.y, v2 = v2f;
        float c0 = v1 * d2 - v2 * d1;
        float c1 = v2 * d0 - v0 * d2;
        float c2 = v0 * d1 - v1 * d0;
        av0 += v0 * q0 + c0 * q1 + d0 * q2;
        av1 += v1 * q0 + c1 * q1 + d1 * q2;
        av2 += v2 * q0 + c2 * q1 + d2 * q2;
        aa  += q3;
    }
    out_a[(size_t)(b * A + a) * 64 + f] = aa;
    float* OV = out_v + (size_t)((b * A + a) * 64 + f) * 3;
    OV[0] = av0;
    OV[1] = av1;
    OV[2] = av2;
}

// ---------------- launch ------------------------------------------------------
extern "C" void kernel_launch(void* const* d_in, const int* in_sizes, int n_in,
                              void* d_out, int out_size) {
    const float* x_a  = (const float*)d_in[0];
    const float* x_v  = (const float*)d_in[1];
    const float* r_ij = (const float*)d_in[2];
    const int*   src  = (const int*)d_in[3];
    const int*   dst  = (const int*)d_in[4];
    const float* dW1 = (const float*)d_in[5];
    const float* db1 = (const float*)d_in[6];
    const float* dW2 = (const float*)d_in[7];
    const float* db2 = (const float*)d_in[8];
    const float* dW3 = (const float*)d_in[9];
    const float* db3 = (const float*)d_in[10];
    const float* aW1 = (const float*)d_in[11];
    const float* ab1 = (const float*)d_in[12];
    const float* aW2 = (const float*)d_in[13];
    const float* ab2 = (const float*)d_in[14];
    const float* aW3 = (const float*)d_in[15];
    const float* ab3 = (const float*)d_in[16];

    const int E  = in_sizes[3];
    const int BA = in_sizes[0] / NFEAT;
    const int A  = BA / 4;                 // B = 4

    __half *te_h, *te_l, *xa_h, *xa_l, *wh, *tp, *pk;
    float4 *sep;
    int *sdst;
    cudaGetSymbolAddress((void**)&te_h, g_te_h);
    cudaGetSymbolAddress((void**)&te_l, g_te_l);
    cudaGetSymbolAddress((void**)&xa_h, g_xa_h);
    cudaGetSymbolAddress((void**)&xa_l, g_xa_l);
    cudaGetSymbolAddress((void**)&wh, g_wh);
    cudaGetSymbolAddress((void**)&tp, g_tp);
    cudaGetSymbolAddress((void**)&pk, g_pk);
    cudaGetSymbolAddress((void**)&sep, g_sep);
    cudaGetSymbolAddress((void**)&sdst, g_sdst);

    cudaFuncSetAttribute(fused_kernel, cudaFuncAttributeMaxDynamicSharedMemorySize, FSMEM);

    // 1) zero histogram
    zero_kernel<<<(A + 1 + 255) / 256, 256>>>(A);

    // 2) prep (tencode + split + wtrans) + hist aux
    const int S1 = (BA * 64) / 256;
    prep_kernel<<<(NTAB * 64 / 256) + S1 + 1152 + 128, 256>>>(
        x_a, dW1, dW2, dW3, aW1, aW2, aW3, src, BA, E);

    // 3) scan
    scan_kernel<<<1, 256>>>(A);

    // 4) fused 3-layer MLP (both chains) + scatter aux + xv-pack aux
    const int nA = BA / 64;
    const int nT = NTAB / 64;
    Chain ca = { xa_h, xa_l, wh + 3 * SLOT, wh + 4 * SLOT, wh + 5 * SLOT, ab1, ab2, ab3 };
    Chain ct = { te_h, te_l, wh + 0 * SLOT, wh + 1 * SLOT, wh + 2 * SLOT, db1, db2, db3 };
    fused_kernel<<<nA + nT + 256, 512, FSMEM>>>(ca, ct, nA, nT,
                                                src, dst, r_ij, x_v, E, A, BA);

    // 5) gather
    float* out_a = (float*)d_out;
    float* out_v = (float*)d_out + (size_t)BA * NFEAT;
    gather_kernel<<<A, 256>>>((const uint4*)tp, (const uint4*)pk,
                              (const float4*)sep, (const int*)sdst, out_a, out_v, A);
}

// round 14
// speedup vs baseline: 1.1445x; 1.0141x over previous
#include <cuda_runtime.h>
#include <cuda_fp16.h>
#include <cstdint>

#define NFEAT 64
#define NHID  256
#define EMAX  320000
#define AMAX  10000
#define BAMAX 40000
#define EPS_F 0.1f
#define COEF0 0.31415926535897931f   // pi / R0, R0 = 10
#define NTAB  4096
#define DMAX  10.0f
#define TSCALE ((float)NTAB / DMAX)
#define SLOT  (256 * 256)

// ---------------- scratch (device globals; zero-initialized at load) ----------
__device__ __half g_te_h[(size_t)NTAB * 64];
__device__ __half g_te_l[(size_t)NTAB * 64];
__device__ __half g_xa_h[(size_t)BAMAX * 64];
__device__ __half g_xa_l[(size_t)BAMAX * 64];
__device__ __half g_tp[(size_t)NTAB * 64 * 8];    // paired table records
__device__ __half g_pk[(size_t)BAMAX * 64 * 8];   // packed row records
__device__ float4 g_sep[EMAX];
__device__ int    g_sdst[EMAX];
__device__ __half g_wh[6 * SLOT];
__device__ int g_cnt[AMAX + 1];                    // zeroed by gather each run
__device__ int g_off[AMAX + 1];
__device__ int g_pos[AMAX];

// ---------------- PTX helpers -------------------------------------------------
__device__ __forceinline__ uint32_t smem_u32(const void* p) {
    uint32_t a;
    asm("{ .reg .u64 t; cvta.to.shared.u64 t, %1; cvt.u32.u64 %0, t; }" : "=r"(a) : "l"(p));
    return a;
}
#define CP16(saddr, gptr) \
    asm volatile("cp.async.cg.shared.global [%0], [%1], 16;" :: "r"(saddr), "l"(gptr) : "memory")
#define CP_COMMIT asm volatile("cp.async.commit_group;" ::: "memory")
#define CP_WAIT0 asm volatile("cp.async.wait_group 0;" ::: "memory")
#define CP_WAIT1 asm volatile("cp.async.wait_group 1;" ::: "memory")

__device__ __forceinline__ void ldsm_x4(uint32_t* r, uint32_t addr) {
    asm volatile("ldmatrix.sync.aligned.m8n8.x4.shared.b16 {%0,%1,%2,%3}, [%4];"
                 : "=r"(r[0]), "=r"(r[1]), "=r"(r[2]), "=r"(r[3]) : "r"(addr));
}
__device__ __forceinline__ void mma16816(float* c, const uint32_t* a, uint32_t b0, uint32_t b1) {
    asm volatile("mma.sync.aligned.m16n8k16.row.col.f32.f16.f16.f32 "
                 "{%0,%1,%2,%3}, {%4,%5,%6,%7}, {%8,%9}, {%0,%1,%2,%3};"
                 : "+f"(c[0]), "+f"(c[1]), "+f"(c[2]), "+f"(c[3])
                 : "r"(a[0]), "r"(a[1]), "r"(a[2]), "r"(a[3]), "r"(b0), "r"(b1));
}
__device__ __forceinline__ void split_h(float v, __half& h, __half& l) {
    h = __float2half_rn(v);
    l = __float2half_rn(v - __half2float(h));
}

// ---------------- scan (512 threads) ------------------------------------------
__global__ void scan_kernel(int A) {
    __shared__ int sh[512];
    int tid = threadIdx.x;
    int chunk = (A + 511) >> 9;
    int base = tid * chunk;
    int sum = 0;
    for (int j = 0; j < chunk; j++) {
        int idx = base + j;
        if (idx < A) sum += g_cnt[idx];
    }
    sh[tid] = sum;
    __syncthreads();
    for (int off = 1; off < 512; off <<= 1) {
        int v = 0;
        if (tid >= off) v = sh[tid - off];
        __syncthreads();
        sh[tid] += v;
        __syncthreads();
    }
    int run = (tid == 0) ? 0 : sh[tid - 1];
    for (int j = 0; j < chunk; j++) {
        int idx = base + j;
        if (idx < A) {
            g_off[idx] = run;
            g_pos[idx] = run;
            run += g_cnt[idx];
        }
    }
    if (base < A && A <= base + chunk) g_off[A] = run;
}

// ---------------- prep: tencode + split(x_a,f4) + wtrans + xv-pack + hist -----
__global__ void prep_kernel(
    const float* __restrict__ x_a, const float* __restrict__ x_v,
    const float* __restrict__ dW1, const float* __restrict__ dW2, const float* __restrict__ dW3,
    const float* __restrict__ aW1, const float* __restrict__ aW2, const float* __restrict__ aW3,
    const int* __restrict__ src, int BA, int E)
{
    const int tid = threadIdx.x;
    int bid = blockIdx.x;
    const int S0 = NTAB * 64 / 256;          // 1024 tencode CTAs
    const int S1 = (BA * 64) / 1024;         // x_a split, float4 per thread
    const int S2 = (BA * 64) / 512;          // xv pack, 2 records per thread

    if (bid < S0) {
        int t = bid * 256 + tid;
        int k = t >> 6, j = t & 63;
        float d = (float)k * (DMAX / (float)NTAB);
        int kk = j & 31;
        float ph = (float)(1 + (kk >> 1)) * COEF0 * d;
        float v = (j < 32) ? cosf(ph) : sinf(ph);
        __half h, l;
        split_h(v, h, l);
        g_te_h[t] = h; g_te_l[t] = l;
        return;
    }
    bid -= S0;
    if (bid < S1) {
        int t = bid * 256 + tid;             // float4 index
        float4 v4 = ((const float4*)x_a)[t];
        __half h0, l0, h1, l1, h2, l2, h3, l3;
        split_h(v4.x, h0, l0); split_h(v4.y, h1, l1);
        split_h(v4.z, h2, l2); split_h(v4.w, h3, l3);
        __half2* dh = (__half2*)&g_xa_h[(size_t)t * 4];
        __half2* dl = (__half2*)&g_xa_l[(size_t)t * 4];
        dh[0] = __halves2half2(h0, h1); dh[1] = __halves2half2(h2, h3);
        dl[0] = __halves2half2(l0, l1); dl[1] = __halves2half2(l2, l3);
        return;
    }
    bid -= S1;
    if (bid < S2) {
        // xv pack: 2 records per thread (6 floats -> 2x half4 in g_pk[8..16))
        int t0 = (bid * 256 + tid) * 2;
#pragma unroll
        for (int u = 0; u < 2; u++) {
            int t = t0 + u;
            float v0 = x_v[(size_t)t * 3 + 0];
            float v1 = x_v[(size_t)t * 3 + 1];
            float v2 = x_v[(size_t)t * 3 + 2];
            __half2* d2 = (__half2*)&g_pk[(size_t)t * 8 + 4];
            d2[0] = __floats2half2_rn(v0, v1);
            d2[1] = __floats2half2_rn(v2, 0.f);
        }
        return;
    }
    bid -= S2;
    if (bid < 1152) {
        const float* W; int K, slot;
        if      (bid < 64)  { W = dW1; K = 64;  slot = 0; }
        else if (bid < 320) { W = dW2; K = 256; slot = 1; bid -= 64; }
        else if (bid < 576) { W = dW3; K = 256; slot = 2; bid -= 320; }
        else if (bid < 640) { W = aW1; K = 64;  slot = 3; bid -= 576; }
        else if (bid < 896) { W = aW2; K = 256; slot = 4; bid -= 640; }
        else                { W = aW3; K = 256; slot = 5; bid -= 896; }
        int t = bid * 256 + tid;
        int n = t & 255, k = t >> 8;
        g_wh[(size_t)slot * SLOT + (size_t)n * K + k] =
            __float2half_rn(W[(size_t)k * 256 + n]);
        return;
    }
    bid -= 1152;
    // hist aux (128 CTAs); g_cnt zeroed by gather at end of previous run
    for (int t = bid * 256 + tid; t < E; t += 128 * 256)
        atomicAdd(&g_cnt[src[t]], 1);
}

// ---------------- fused 3-layer MLP kernel ------------------------------------
#define XROWB 528
#define XA_HI 0
#define XB_HI 67584
#define LODELTA 33792
#define BST0  135168
#define BST1  172032
#define FSMEM 208896
#define BROWB 144
#define NSTEP 9

struct Chain {
    const __half* inh; const __half* inl;
    const __half* W1; const __half* W2; const __half* W3;
    const float* b1; const float* b2; const float* b3;
};

__global__ void __launch_bounds__(512, 1) fused_kernel(
    Chain ca, Chain ct, int nA, int nT,
    const int* __restrict__ src, const int* __restrict__ dst,
    const float* __restrict__ r_ij,
    int E, int A, int BA)
{
    extern __shared__ char smem[];
    const int tid = threadIdx.x;
    int bid = blockIdx.x;

    if (bid >= nA + nT) {
        int abid = bid - (nA + nT);
        // payload scatter (128 CTAs)
        for (int t = abid * 512 + tid; t < E; t += 128 * 512) {
            float rx = r_ij[(size_t)t * 3 + 0];
            float ry = r_ij[(size_t)t * 3 + 1];
            float rz = r_ij[(size_t)t * 3 + 2];
            float d2s = rx * rx + ry * ry + rz * rz;
            float d = sqrtf(d2s);
            float inv = rsqrtf(EPS_F + d2s);
            float idxf = d * TSCALE;
            if (idxf > (float)(NTAB - 1) - 1e-3f) idxf = (float)(NTAB - 1) - 1e-3f;
            int pp = atomicAdd(&g_pos[src[t]], 1);
            g_sep[pp] = make_float4(rx * inv, ry * inv, rz * inv, idxf);
            g_sdst[pp] = dst[t];
        }
        return;
    }

    const bool isA = bid < nA;
    const Chain C = isA ? ca : ct;
    const int row0 = (isA ? bid : bid - nA) * 64;

    const uint32_t sbase = smem_u32(smem);
    const int lane = tid & 31;
    const int wid = tid >> 5;
    const int warp_m = wid & 3;
    const int warp_n = wid >> 2;

    const uint32_t arow = (uint32_t)(warp_m * 16 + (lane & 15));
    const uint32_t asub = (uint32_t)((lane >> 4) << 4);
    const uint32_t boff = (uint32_t)(warp_n * 64 + (lane & 7) + ((lane >> 4) << 3)) * BROWB
                        + (((lane >> 3) & 1) << 4);

    const __half* Ws[3] = { C.W1, C.W2, C.W3 };
    const float* Bs[3] = { C.b1, C.b2, C.b3 };

    // A0 input staging (hi/lo, pitch 144) into XB region
    {
        int r = tid >> 3, cs = tid & 7;
        size_t ga = (size_t)(row0 + r) * 64 + cs * 8;
        uint32_t so = (uint32_t)r * BROWB + cs * 16;
        CP16(sbase + XB_HI + so, C.inh + ga);
        CP16(sbase + XB_HI + LODELTA + so, C.inl + ga);
    }

    auto load_B = [&](int slot, int s) {
        int L, kb, K;
        if (s == 0)     { L = 0; kb = 0;            K = 64; }
        else if (s < 5) { L = 1; kb = (s - 1) * 64; K = 256; }
        else            { L = 2; kb = (s - 5) * 64; K = 256; }
        const __half* W = Ws[L];
        uint32_t sb = sbase + (slot ? BST1 : BST0);
#pragma unroll
        for (int it = 0; it < 4; it++) {
            int idx = tid + it * 512;
            int r = idx >> 3, cs = idx & 7;
            CP16(sb + (uint32_t)r * BROWB + cs * 16,
                 W + (size_t)r * K + kb + cs * 8);
        }
    };

    load_B(0, 0); CP_COMMIT;
    load_B(1, 1); CP_COMMIT;

    float acc[8][4];

    for (int s = 0; s < NSTEP; s++) {
        int L, c, last;
        if (s == 0)     { L = 0; c = 0;     last = 1; }
        else if (s < 5) { L = 1; c = s - 1; last = (c == 3); }
        else            { L = 2; c = s - 5; last = (c == 3); }

        if (s + 1 < NSTEP) { CP_WAIT1; } else { CP_WAIT0; }
        __syncthreads();

        if (c == 0) {
#pragma unroll
            for (int tn = 0; tn < 8; tn++)
#pragma unroll
                for (int j = 0; j < 4; j++) acc[tn][j] = 0.f;
        }

        uint32_t ab;
        if (L == 0) ab = sbase + XB_HI + arow * BROWB + asub;
        else {
            uint32_t xh = (L == 1) ? XA_HI : XB_HI;
            ab = sbase + xh + arow * XROWB + asub + c * 128;
        }
        const uint32_t albase = ab + LODELTA;
        const uint32_t bbb = sbase + ((s & 1) ? BST1 : BST0) + boff;

#pragma unroll
        for (int ks = 0; ks < 4; ks++) {
            uint32_t ah[4], al[4], bb[4][4];
            ldsm_x4(ah, ab + ks * 32);
            ldsm_x4(al, albase + ks * 32);
#pragma unroll
            for (int tg = 0; tg < 4; tg++)
                ldsm_x4(bb[tg], bbb + tg * 16 * BROWB + ks * 32);
#pragma unroll
            for (int tn = 0; tn < 8; tn++) {
                uint32_t b0 = bb[tn >> 1][(tn & 1) * 2];
                uint32_t b1 = bb[tn >> 1][(tn & 1) * 2 + 1];
                mma16816(acc[tn], ah, b0, b1);
                mma16816(acc[tn], al, b0, b1);
            }
        }

        if (last) {
            const int act = (L < 2);
#pragma unroll
            for (int tn = 0; tn < 8; tn++) {
                int gcol = warp_n * 64 + tn * 8 + 2 * (lane & 3);
                int r0 = warp_m * 16 + (lane >> 2);
                float b0 = __ldg(&Bs[L][gcol]);
                float b1 = __ldg(&Bs[L][gcol + 1]);
                float v0 = acc[tn][0] + b0;
                float v1 = acc[tn][1] + b1;
                float v2 = acc[tn][2] + b0;
                float v3 = acc[tn][3] + b1;
                if (act) {
                    v0 = v0 / (1.f + __expf(-v0));
                    v1 = v1 / (1.f + __expf(-v1));
                    v2 = v2 / (1.f + __expf(-v2));
                    v3 = v3 / (1.f + __expf(-v3));
                }
                if (L < 2) {
                    const uint32_t xh = (L == 0) ? XA_HI : XB_HI;
                    char* base = smem + xh;
                    __half h0, l0, h1, l1;
                    split_h(v0, h0, l0); split_h(v1, h1, l1);
                    *(__half2*)(base + (size_t)r0 * XROWB + gcol * 2) = __halves2half2(h0, h1);
                    *(__half2*)(base + LODELTA + (size_t)r0 * XROWB + gcol * 2) = __halves2half2(l0, l1);
                    split_h(v2, h0, l0); split_h(v3, h1, l1);
                    *(__half2*)(base + (size_t)(r0 + 8) * XROWB + gcol * 2) = __halves2half2(h0, h1);
                    *(__half2*)(base + LODELTA + (size_t)(r0 + 8) * XROWB + gcol * 2) = __halves2half2(l0, l1);
                } else {
                    __half* sg = (__half*)smem;
                    int f = gcol & 63, role = gcol >> 6;
                    sg[r0 * 260 + f * 4 + role]             = __float2half_rn(v0);
                    sg[r0 * 260 + (f + 1) * 4 + role]       = __float2half_rn(v1);
                    sg[(r0 + 8) * 260 + f * 4 + role]       = __float2half_rn(v2);
                    sg[(r0 + 8) * 260 + (f + 1) * 4 + role] = __float2half_rn(v3);
                }
            }
        }

        if (s + 2 < NSTEP) {
            __syncthreads();
            load_B(s & 1, s + 2);
            CP_COMMIT;
        }
    }

    // final record writes
    __syncthreads();
    __half* sg = (__half*)smem;
    if (isA) {
#pragma unroll
        for (int i = 0; i < 8; i++) {
            int idx = tid + i * 512;
            int rr = idx >> 6, f = idx & 63;
            uint2 w = *(uint2*)&sg[rr * 260 + f * 4];
            *(uint2*)((char*)g_pk + ((size_t)(row0 + rr) * 64 + f) * 16) = w;
        }
    } else {
#pragma unroll
        for (int i = 0; i < 8; i++) {
            int idx = tid + i * 512;
            int rr = idx >> 6, f = idx & 63;
            char* rec = (char*)g_tp + (((size_t)(row0 + rr)) * 64 + f) * 16;
            uint2 lo = *(uint2*)&sg[rr * 260 + f * 4];
            *(uint2*)rec = lo;
            if (rr < 63) {
                uint2 hi = *(uint2*)&sg[(rr + 1) * 260 + f * 4];
                *(uint2*)(rec + 8) = hi;
            }
        }
        if (row0 > 0 && tid < 64) {
            uint2 w0 = *(uint2*)&sg[0 * 260 + tid * 4];
            *(uint2*)((char*)g_tp + ((size_t)(row0 - 1) * 64 + tid) * 16 + 8) = w0;
        }
    }
}

// ---------------- per-atom gather (+ g_cnt re-zero for next run) --------------
__global__ __launch_bounds__(256) void gather_kernel(
    const uint4* __restrict__ TP,
    const uint4* __restrict__ PK,
    const float4* __restrict__ SEP,
    const int* __restrict__ SDST,
    float* __restrict__ out_a, float* __restrict__ out_v, int A)
{
    int a = blockIdx.x;
    int f = threadIdx.x & 63;
    int b = threadIdx.x >> 6;
    int p0 = g_off[a];
    int p1 = g_off[a + 1];

    // re-zero histogram slot for the next graph replay
    if (threadIdx.x == 0) {
        g_cnt[a] = 0;
        if (a == 0) g_cnt[A] = 0;
    }

    float av0 = 0.f, av1 = 0.f, av2 = 0.f, aa = 0.f;
#pragma unroll 2
    for (int p = p0; p < p1; ++p) {
        float4 ed = __ldg(&SEP[p]);
        int dd = __ldg(&SDST[p]);
        float d0 = ed.x, d1 = ed.y, d2 = ed.z;
        int k = (int)ed.w;
        float w = ed.w - (float)k;

        uint4 tv = __ldg(&TP[(size_t)k * 64 + f]);
        float2 t0a = __half22float2(*(__half2*)&tv.x);
        float2 t0b = __half22float2(*(__half2*)&tv.y);
        float2 t1a = __half22float2(*(__half2*)&tv.z);
        float2 t1b = __half22float2(*(__half2*)&tv.w);
        float q0 = fmaf(w, t1a.x - t0a.x, t0a.x);
        float q1 = fmaf(w, t1a.y - t0a.y, t0a.y);
        float q2 = fmaf(w, t1b.x - t0b.x, t0b.x);
        float q3 = fmaf(w, t1b.y - t0b.y, t0b.y);

        uint4 pk = __ldg(&PK[(size_t)(b * A + dd) * 64 + f]);
        __half2 pra = *(__half2*)&pk.x;
        __half2 prb = *(__half2*)&pk.y;
        q0 *= __low2float(pra);
        q1 *= __high2float(pra);
        q2 *= __low2float(prb);
        q3 *= __high2float(prb);

        float2 va = __half22float2(*(__half2*)&pk.z);
        float v2f = __low2float(*(__half2*)&pk.w);
        float v0 = va.x, v1 = va.y, v2 = v2f;
        float c0 = v1 * d2 - v2 * d1;
        float c1 = v2 * d0 - v0 * d2;
        float c2 = v0 * d1 - v1 * d0;
        av0 += v0 * q0 + c0 * q1 + d0 * q2;
        av1 += v1 * q0 + c1 * q1 + d1 * q2;
        av2 += v2 * q0 + c2 * q1 + d2 * q2;
        aa  += q3;
    }
    out_a[(size_t)(b * A + a) * 64 + f] = aa;
    float* OV = out_v + (size_t)((b * A + a) * 64 + f) * 3;
    OV[0] = av0;
    OV[1] = av1;
    OV[2] = av2;
}

// ---------------- launch ------------------------------------------------------
extern "C" void kernel_launch(void* const* d_in, const int* in_sizes, int n_in,
                              void* d_out, int out_size) {
    const float* x_a  = (const float*)d_in[0];
    const float* x_v  = (const float*)d_in[1];
    const float* r_ij = (const float*)d_in[2];
    const int*   src  = (const int*)d_in[3];
    const int*   dst  = (const int*)d_in[4];
    const float* dW1 = (const float*)d_in[5];
    const float* db1 = (const float*)d_in[6];
    const float* dW2 = (const float*)d_in[7];
    const float* db2 = (const float*)d_in[8];
    const float* dW3 = (const float*)d_in[9];
    const float* db3 = (const float*)d_in[10];
    const float* aW1 = (const float*)d_in[11];
    const float* ab1 = (const float*)d_in[12];
    const float* aW2 = (const float*)d_in[13];
    const float* ab2 = (const float*)d_in[14];
    const float* aW3 = (const float*)d_in[15];
    const float* ab3 = (const float*)d_in[16];

    const int E  = in_sizes[3];
    const int BA = in_sizes[0] / NFEAT;
    const int A  = BA / 4;                 // B = 4

    __half *te_h, *te_l, *xa_h, *xa_l, *wh, *tp, *pk;
    float4 *sep;
    int *sdst;
    cudaGetSymbolAddress((void**)&te_h, g_te_h);
    cudaGetSymbolAddress((void**)&te_l, g_te_l);
    cudaGetSymbolAddress((void**)&xa_h, g_xa_h);
    cudaGetSymbolAddress((void**)&xa_l, g_xa_l);
    cudaGetSymbolAddress((void**)&wh, g_wh);
    cudaGetSymbolAddress((void**)&tp, g_tp);
    cudaGetSymbolAddress((void**)&pk, g_pk);
    cudaGetSymbolAddress((void**)&sep, g_sep);
    cudaGetSymbolAddress((void**)&sdst, g_sdst);

    cudaFuncSetAttribute(fused_kernel, cudaFuncAttributeMaxDynamicSharedMemorySize, FSMEM);

    // 1) prep: tencode + x_a split (float4) + xv-pack + wtrans + hist
    const int S1 = (BA * 64) / 1024;
    const int S2 = (BA * 64) / 512;
    prep_kernel<<<(NTAB * 64 / 256) + S1 + S2 + 1152 + 128, 256>>>(
        x_a, x_v, dW1, dW2, dW3, aW1, aW2, aW3, src, BA, E);

    // 2) scan
    scan_kernel<<<1, 512>>>(A);

    // 3) fused 3-layer MLP (both chains) + payload-scatter aux
    const int nA = BA / 64;
    const int nT = NTAB / 64;
    Chain ca = { xa_h, xa_l, wh + 3 * SLOT, wh + 4 * SLOT, wh + 5 * SLOT, ab1, ab2, ab3 };
    Chain ct = { te_h, te_l, wh + 0 * SLOT, wh + 1 * SLOT, wh + 2 * SLOT, db1, db2, db3 };
    fused_kernel<<<nA + nT + 128, 512, FSMEM>>>(ca, ct, nA, nT,
                                                src, dst, r_ij, E, A, BA);

    // 4) gather (also re-zeroes g_cnt for the next replay)
    float* out_a = (float*)d_out;
    float* out_v = (float*)d_out + (size_t)BA * NFEAT;
    gather_kernel<<<A, 256>>>((const uint4*)tp, (const uint4*)pk,
                              (const float4*)sep, (const int*)sdst, out_a, out_v, A);
}

// round 15
// speedup vs baseline: 1.3471x; 1.1770x over previous
#include <cuda_runtime.h>
#include <cuda_fp16.h>
#include <cstdint>

#define NFEAT 64
#define NHID  256
#define EMAX  320000
#define AMAX  10000
#define BAMAX 40000
#define EPS_F 0.1f
#define COEF0 0.31415926535897931f   // pi / R0, R0 = 10
#define NTAB  4096
#define DMAX  10.0f
#define TSCALE ((float)NTAB / DMAX)
#define SLOT  (256 * 256)

// ---------------- scratch (device globals; zero-initialized at load) ----------
__device__ __half g_te_h[(size_t)NTAB * 64];
__device__ __half g_te_l[(size_t)NTAB * 64];
__device__ __half g_xa_h[(size_t)BAMAX * 64];
__device__ __half g_xa_l[(size_t)BAMAX * 64];
__device__ __half g_tp[(size_t)NTAB * 64 * 8];    // paired table records
__device__ __half g_pk[(size_t)BAMAX * 64 * 8];   // packed row records
__device__ float4 g_sep[EMAX];
__device__ int    g_sdst[EMAX];
__device__ __half g_wh[6 * SLOT];
__device__ int g_cnt[AMAX + 1];                    // zeroed by gather each run
__device__ int g_off[AMAX + 1];
__device__ int g_pos[AMAX];

// ---------------- PTX helpers -------------------------------------------------
__device__ __forceinline__ uint32_t smem_u32(const void* p) {
    uint32_t a;
    asm("{ .reg .u64 t; cvta.to.shared.u64 t, %1; cvt.u32.u64 %0, t; }" : "=r"(a) : "l"(p));
    return a;
}
#define CP16(saddr, gptr) \
    asm volatile("cp.async.cg.shared.global [%0], [%1], 16;" :: "r"(saddr), "l"(gptr) : "memory")
#define CP_COMMIT asm volatile("cp.async.commit_group;" ::: "memory")
#define CP_WAIT0 asm volatile("cp.async.wait_group 0;" ::: "memory")
#define CP_WAIT1 asm volatile("cp.async.wait_group 1;" ::: "memory")

__device__ __forceinline__ void ldsm_x4(uint32_t* r, uint32_t addr) {
    asm volatile("ldmatrix.sync.aligned.m8n8.x4.shared.b16 {%0,%1,%2,%3}, [%4];"
                 : "=r"(r[0]), "=r"(r[1]), "=r"(r[2]), "=r"(r[3]) : "r"(addr));
}
__device__ __forceinline__ void mma16816(float* c, const uint32_t* a, uint32_t b0, uint32_t b1) {
    asm volatile("mma.sync.aligned.m16n8k16.row.col.f32.f16.f16.f32 "
                 "{%0,%1,%2,%3}, {%4,%5,%6,%7}, {%8,%9}, {%0,%1,%2,%3};"
                 : "+f"(c[0]), "+f"(c[1]), "+f"(c[2]), "+f"(c[3])
                 : "r"(a[0]), "r"(a[1]), "r"(a[2]), "r"(a[3]), "r"(b0), "r"(b1));
}
__device__ __forceinline__ void split_h(float v, __half& h, __half& l) {
    h = __float2half_rn(v);
    l = __float2half_rn(v - __half2float(h));
}

// ---------------- scan (512 threads) ------------------------------------------
__global__ void scan_kernel(int A) {
    __shared__ int sh[512];
    int tid = threadIdx.x;
    int chunk = (A + 511) >> 9;
    int base = tid * chunk;
    int sum = 0;
    for (int j = 0; j < chunk; j++) {
        int idx = base + j;
        if (idx < A) sum += g_cnt[idx];
    }
    sh[tid] = sum;
    __syncthreads();
    for (int off = 1; off < 512; off <<= 1) {
        int v = 0;
        if (tid >= off) v = sh[tid - off];
        __syncthreads();
        sh[tid] += v;
        __syncthreads();
    }
    int run = (tid == 0) ? 0 : sh[tid - 1];
    for (int j = 0; j < chunk; j++) {
        int idx = base + j;
        if (idx < A) {
            g_off[idx] = run;
            g_pos[idx] = run;
            run += g_cnt[idx];
        }
    }
    if (base < A && A <= base + chunk) g_off[A] = run;
}

// ---------------- prep: tencode + split(x_a,f4) + wtrans + xv-pack + hist -----
__global__ void prep_kernel(
    const float* __restrict__ x_a, const float* __restrict__ x_v,
    const float* __restrict__ dW1, const float* __restrict__ dW2, const float* __restrict__ dW3,
    const float* __restrict__ aW1, const float* __restrict__ aW2, const float* __restrict__ aW3,
    const int* __restrict__ src, int BA, int E)
{
    const int tid = threadIdx.x;
    int bid = blockIdx.x;
    const int S0 = NTAB * 64 / 256;
    const int S1 = (BA * 64) / 1024;
    const int S2 = (BA * 64) / 512;

    if (bid < S0) {
        int t = bid * 256 + tid;
        int k = t >> 6, j = t & 63;
        float d = (float)k * (DMAX / (float)NTAB);
        int kk = j & 31;
        float ph = (float)(1 + (kk >> 1)) * COEF0 * d;
        float v = (j < 32) ? cosf(ph) : sinf(ph);
        __half h, l;
        split_h(v, h, l);
        g_te_h[t] = h; g_te_l[t] = l;
        return;
    }
    bid -= S0;
    if (bid < S1) {
        int t = bid * 256 + tid;
        float4 v4 = ((const float4*)x_a)[t];
        __half h0, l0, h1, l1, h2, l2, h3, l3;
        split_h(v4.x, h0, l0); split_h(v4.y, h1, l1);
        split_h(v4.z, h2, l2); split_h(v4.w, h3, l3);
        __half2* dh = (__half2*)&g_xa_h[(size_t)t * 4];
        __half2* dl = (__half2*)&g_xa_l[(size_t)t * 4];
        dh[0] = __halves2half2(h0, h1); dh[1] = __halves2half2(h2, h3);
        dl[0] = __halves2half2(l0, l1); dl[1] = __halves2half2(l2, l3);
        return;
    }
    bid -= S1;
    if (bid < S2) {
        int t0 = (bid * 256 + tid) * 2;
#pragma unroll
        for (int u = 0; u < 2; u++) {
            int t = t0 + u;
            float v0 = x_v[(size_t)t * 3 + 0];
            float v1 = x_v[(size_t)t * 3 + 1];
            float v2 = x_v[(size_t)t * 3 + 2];
            __half2* d2 = (__half2*)&g_pk[(size_t)t * 8 + 4];
            d2[0] = __floats2half2_rn(v0, v1);
            d2[1] = __floats2half2_rn(v2, 0.f);
        }
        return;
    }
    bid -= S2;
    if (bid < 1152) {
        const float* W; int K, slot;
        if      (bid < 64)  { W = dW1; K = 64;  slot = 0; }
        else if (bid < 320) { W = dW2; K = 256; slot = 1; bid -= 64; }
        else if (bid < 576) { W = dW3; K = 256; slot = 2; bid -= 320; }
        else if (bid < 640) { W = aW1; K = 64;  slot = 3; bid -= 576; }
        else if (bid < 896) { W = aW2; K = 256; slot = 4; bid -= 640; }
        else                { W = aW3; K = 256; slot = 5; bid -= 896; }
        int t = bid * 256 + tid;
        int n = t & 255, k = t >> 8;
        g_wh[(size_t)slot * SLOT + (size_t)n * K + k] =
            __float2half_rn(W[(size_t)k * 256 + n]);
        return;
    }
    bid -= 1152;
    for (int t = bid * 256 + tid; t < E; t += 128 * 256)
        atomicAdd(&g_cnt[src[t]], 1);
}

// ---------------- fused 3-layer MLP kernel (unchanged from R14) ---------------
#define XROWB 528
#define XA_HI 0
#define XB_HI 67584
#define LODELTA 33792
#define BST0  135168
#define BST1  172032
#define FSMEM 208896
#define BROWB 144
#define NSTEP 9

struct Chain {
    const __half* inh; const __half* inl;
    const __half* W1; const __half* W2; const __half* W3;
    const float* b1; const float* b2; const float* b3;
};

__global__ void __launch_bounds__(512, 1) fused_kernel(
    Chain ca, Chain ct, int nA, int nT,
    const int* __restrict__ src, const int* __restrict__ dst,
    const float* __restrict__ r_ij,
    int E, int A, int BA)
{
    extern __shared__ char smem[];
    const int tid = threadIdx.x;
    int bid = blockIdx.x;

    if (bid >= nA + nT) {
        int abid = bid - (nA + nT);
        for (int t = abid * 512 + tid; t < E; t += 128 * 512) {
            float rx = r_ij[(size_t)t * 3 + 0];
            float ry = r_ij[(size_t)t * 3 + 1];
            float rz = r_ij[(size_t)t * 3 + 2];
            float d2s = rx * rx + ry * ry + rz * rz;
            float d = sqrtf(d2s);
            float inv = rsqrtf(EPS_F + d2s);
            float idxf = d * TSCALE;
            if (idxf > (float)(NTAB - 1) - 1e-3f) idxf = (float)(NTAB - 1) - 1e-3f;
            int pp = atomicAdd(&g_pos[src[t]], 1);
            g_sep[pp] = make_float4(rx * inv, ry * inv, rz * inv, idxf);
            g_sdst[pp] = dst[t];
        }
        return;
    }

    const bool isA = bid < nA;
    const Chain C = isA ? ca : ct;
    const int row0 = (isA ? bid : bid - nA) * 64;

    const uint32_t sbase = smem_u32(smem);
    const int lane = tid & 31;
    const int wid = tid >> 5;
    const int warp_m = wid & 3;
    const int warp_n = wid >> 2;

    const uint32_t arow = (uint32_t)(warp_m * 16 + (lane & 15));
    const uint32_t asub = (uint32_t)((lane >> 4) << 4);
    const uint32_t boff = (uint32_t)(warp_n * 64 + (lane & 7) + ((lane >> 4) << 3)) * BROWB
                        + (((lane >> 3) & 1) << 4);

    const __half* Ws[3] = { C.W1, C.W2, C.W3 };
    const float* Bs[3] = { C.b1, C.b2, C.b3 };

    {
        int r = tid >> 3, cs = tid & 7;
        size_t ga = (size_t)(row0 + r) * 64 + cs * 8;
        uint32_t so = (uint32_t)r * BROWB + cs * 16;
        CP16(sbase + XB_HI + so, C.inh + ga);
        CP16(sbase + XB_HI + LODELTA + so, C.inl + ga);
    }

    auto load_B = [&](int slot, int s) {
        int L, kb, K;
        if (s == 0)     { L = 0; kb = 0;            K = 64; }
        else if (s < 5) { L = 1; kb = (s - 1) * 64; K = 256; }
        else            { L = 2; kb = (s - 5) * 64; K = 256; }
        const __half* W = Ws[L];
        uint32_t sb = sbase + (slot ? BST1 : BST0);
#pragma unroll
        for (int it = 0; it < 4; it++) {
            int idx = tid + it * 512;
            int r = idx >> 3, cs = idx & 7;
            CP16(sb + (uint32_t)r * BROWB + cs * 16,
                 W + (size_t)r * K + kb + cs * 8);
        }
    };

    load_B(0, 0); CP_COMMIT;
    load_B(1, 1); CP_COMMIT;

    float acc[8][4];

    for (int s = 0; s < NSTEP; s++) {
        int L, c, last;
        if (s == 0)     { L = 0; c = 0;     last = 1; }
        else if (s < 5) { L = 1; c = s - 1; last = (c == 3); }
        else            { L = 2; c = s - 5; last = (c == 3); }

        if (s + 1 < NSTEP) { CP_WAIT1; } else { CP_WAIT0; }
        __syncthreads();

        if (c == 0) {
#pragma unroll
            for (int tn = 0; tn < 8; tn++)
#pragma unroll
                for (int j = 0; j < 4; j++) acc[tn][j] = 0.f;
        }

        uint32_t ab;
        if (L == 0) ab = sbase + XB_HI + arow * BROWB + asub;
        else {
            uint32_t xh = (L == 1) ? XA_HI : XB_HI;
            ab = sbase + xh + arow * XROWB + asub + c * 128;
        }
        const uint32_t albase = ab + LODELTA;
        const uint32_t bbb = sbase + ((s & 1) ? BST1 : BST0) + boff;

#pragma unroll
        for (int ks = 0; ks < 4; ks++) {
            uint32_t ah[4], al[4], bb[4][4];
            ldsm_x4(ah, ab + ks * 32);
            ldsm_x4(al, albase + ks * 32);
#pragma unroll
            for (int tg = 0; tg < 4; tg++)
                ldsm_x4(bb[tg], bbb + tg * 16 * BROWB + ks * 32);
#pragma unroll
            for (int tn = 0; tn < 8; tn++) {
                uint32_t b0 = bb[tn >> 1][(tn & 1) * 2];
                uint32_t b1 = bb[tn >> 1][(tn & 1) * 2 + 1];
                mma16816(acc[tn], ah, b0, b1);
                mma16816(acc[tn], al, b0, b1);
            }
        }

        if (last) {
            const int act = (L < 2);
#pragma unroll
            for (int tn = 0; tn < 8; tn++) {
                int gcol = warp_n * 64 + tn * 8 + 2 * (lane & 3);
                int r0 = warp_m * 16 + (lane >> 2);
                float b0 = __ldg(&Bs[L][gcol]);
                float b1 = __ldg(&Bs[L][gcol + 1]);
                float v0 = acc[tn][0] + b0;
                float v1 = acc[tn][1] + b1;
                float v2 = acc[tn][2] + b0;
                float v3 = acc[tn][3] + b1;
                if (act) {
                    v0 = v0 / (1.f + __expf(-v0));
                    v1 = v1 / (1.f + __expf(-v1));
                    v2 = v2 / (1.f + __expf(-v2));
                    v3 = v3 / (1.f + __expf(-v3));
                }
                if (L < 2) {
                    const uint32_t xh = (L == 0) ? XA_HI : XB_HI;
                    char* base = smem + xh;
                    __half h0, l0, h1, l1;
                    split_h(v0, h0, l0); split_h(v1, h1, l1);
                    *(__half2*)(base + (size_t)r0 * XROWB + gcol * 2) = __halves2half2(h0, h1);
                    *(__half2*)(base + LODELTA + (size_t)r0 * XROWB + gcol * 2) = __halves2half2(l0, l1);
                    split_h(v2, h0, l0); split_h(v3, h1, l1);
                    *(__half2*)(base + (size_t)(r0 + 8) * XROWB + gcol * 2) = __halves2half2(h0, h1);
                    *(__half2*)(base + LODELTA + (size_t)(r0 + 8) * XROWB + gcol * 2) = __halves2half2(l0, l1);
                } else {
                    __half* sg = (__half*)smem;
                    int f = gcol & 63, role = gcol >> 6;
                    sg[r0 * 260 + f * 4 + role]             = __float2half_rn(v0);
                    sg[r0 * 260 + (f + 1) * 4 + role]       = __float2half_rn(v1);
                    sg[(r0 + 8) * 260 + f * 4 + role]       = __float2half_rn(v2);
                    sg[(r0 + 8) * 260 + (f + 1) * 4 + role] = __float2half_rn(v3);
                }
            }
        }

        if (s + 2 < NSTEP) {
            __syncthreads();
            load_B(s & 1, s + 2);
            CP_COMMIT;
        }
    }

    __syncthreads();
    __half* sg = (__half*)smem;
    if (isA) {
#pragma unroll
        for (int i = 0; i < 8; i++) {
            int idx = tid + i * 512;
            int rr = idx >> 6, f = idx & 63;
            uint2 w = *(uint2*)&sg[rr * 260 + f * 4];
            *(uint2*)((char*)g_pk + ((size_t)(row0 + rr) * 64 + f) * 16) = w;
        }
    } else {
#pragma unroll
        for (int i = 0; i < 8; i++) {
            int idx = tid + i * 512;
            int rr = idx >> 6, f = idx & 63;
            char* rec = (char*)g_tp + (((size_t)(row0 + rr)) * 64 + f) * 16;
            uint2 lo = *(uint2*)&sg[rr * 260 + f * 4];
            *(uint2*)rec = lo;
            if (rr < 63) {
                uint2 hi = *(uint2*)&sg[(rr + 1) * 260 + f * 4];
                *(uint2*)(rec + 8) = hi;
            }
        }
        if (row0 > 0 && tid < 64) {
            uint2 w0 = *(uint2*)&sg[0 * 260 + tid * 4];
            *(uint2*)((char*)g_tp + ((size_t)(row0 - 1) * 64 + tid) * 16 + 8) = w0;
        }
    }
}

// ---------------- per-atom gather: 64 threads, batch-loop dedups lerp ---------
__global__ __launch_bounds__(64) void gather_kernel(
    const uint4* __restrict__ TP,
    const uint4* __restrict__ PK,
    const float4* __restrict__ SEP,
    const int* __restrict__ SDST,
    float* __restrict__ out_a, float* __restrict__ out_v, int A)
{
    int a = blockIdx.x;
    int f = threadIdx.x;     // 0..63
    int p0 = g_off[a];
    int p1 = g_off[a + 1];

    // re-zero histogram slot for the next graph replay
    if (f == 0) {
        g_cnt[a] = 0;
        if (a == 0) g_cnt[A] = 0;
    }

    float av[4][3];
    float aa[4];
#pragma unroll
    for (int b = 0; b < 4; b++) {
        av[b][0] = 0.f; av[b][1] = 0.f; av[b][2] = 0.f; aa[b] = 0.f;
    }

#pragma unroll 2
    for (int p = p0; p < p1; ++p) {
        float4 ed = __ldg(&SEP[p]);
        int dd = __ldg(&SDST[p]);
        float d0 = ed.x, d1 = ed.y, d2 = ed.z;
        int k = (int)ed.w;
        float w = ed.w - (float)k;

        // table lerp: computed ONCE per (edge, f), shared across 4 batches
        uint4 tv = __ldg(&TP[(size_t)k * 64 + f]);
        float2 t0a = __half22float2(*(__half2*)&tv.x);
        float2 t0b = __half22float2(*(__half2*)&tv.y);
        float2 t1a = __half22float2(*(__half2*)&tv.z);
        float2 t1b = __half22float2(*(__half2*)&tv.w);
        float q0t = fmaf(w, t1a.x - t0a.x, t0a.x);
        float q1t = fmaf(w, t1a.y - t0a.y, t0a.y);
        float q2t = fmaf(w, t1b.x - t0b.x, t0b.x);
        float q3t = fmaf(w, t1b.y - t0b.y, t0b.y);

        size_t rbase = (size_t)dd * 64 + f;
#pragma unroll
        for (int b = 0; b < 4; b++) {
            uint4 pk = __ldg(&PK[rbase + (size_t)b * A * 64]);
            __half2 pra = *(__half2*)&pk.x;
            __half2 prb = *(__half2*)&pk.y;
            float q0 = q0t * __low2float(pra);
            float q1 = q1t * __high2float(pra);
            float q2 = q2t * __low2float(prb);
            float q3 = q3t * __high2float(prb);

            float2 va = __half22float2(*(__half2*)&pk.z);
            float v2f = __low2float(*(__half2*)&pk.w);
            float v0 = va.x, v1 = va.y, v2 = v2f;
            float c0 = v1 * d2 - v2 * d1;
            float c1 = v2 * d0 - v0 * d2;
            float c2 = v0 * d1 - v1 * d0;
            av[b][0] += v0 * q0 + c0 * q1 + d0 * q2;
            av[b][1] += v1 * q0 + c1 * q1 + d1 * q2;
            av[b][2] += v2 * q0 + c2 * q1 + d2 * q2;
            aa[b]    += q3;
        }
    }

#pragma unroll
    for (int b = 0; b < 4; b++) {
        out_a[(size_t)(b * A + a) * 64 + f] = aa[b];
        float* OV = out_v + (size_t)((b * A + a) * 64 + f) * 3;
        OV[0] = av[b][0];
        OV[1] = av[b][1];
        OV[2] = av[b][2];
    }
}

// ---------------- launch ------------------------------------------------------
extern "C" void kernel_launch(void* const* d_in, const int* in_sizes, int n_in,
                              void* d_out, int out_size) {
    const float* x_a  = (const float*)d_in[0];
    const float* x_v  = (const float*)d_in[1];
    const float* r_ij = (const float*)d_in[2];
    const int*   src  = (const int*)d_in[3];
    const int*   dst  = (const int*)d_in[4];
    const float* dW1 = (const float*)d_in[5];
    const float* db1 = (const float*)d_in[6];
    const float* dW2 = (const float*)d_in[7];
    const float* db2 = (const float*)d_in[8];
    const float* dW3 = (const float*)d_in[9];
    const float* db3 = (const float*)d_in[10];
    const float* aW1 = (const float*)d_in[11];
    const float* ab1 = (const float*)d_in[12];
    const float* aW2 = (const float*)d_in[13];
    const float* ab2 = (const float*)d_in[14];
    const float* aW3 = (const float*)d_in[15];
    const float* ab3 = (const float*)d_in[16];

    const int E  = in_sizes[3];
    const int BA = in_sizes[0] / NFEAT;
    const int A  = BA / 4;                 // B = 4

    __half *te_h, *te_l, *xa_h, *xa_l, *wh, *tp, *pk;
    float4 *sep;
    int *sdst;
    cudaGetSymbolAddress((void**)&te_h, g_te_h);
    cudaGetSymbolAddress((void**)&te_l, g_te_l);
    cudaGetSymbolAddress((void**)&xa_h, g_xa_h);
    cudaGetSymbolAddress((void**)&xa_l, g_xa_l);
    cudaGetSymbolAddress((void**)&wh, g_wh);
    cudaGetSymbolAddress((void**)&tp, g_tp);
    cudaGetSymbolAddress((void**)&pk, g_pk);
    cudaGetSymbolAddress((void**)&sep, g_sep);
    cudaGetSymbolAddress((void**)&sdst, g_sdst);

    cudaFuncSetAttribute(fused_kernel, cudaFuncAttributeMaxDynamicSharedMemorySize, FSMEM);

    // 1) prep
    const int S1 = (BA * 64) / 1024;
    const int S2 = (BA * 64) / 512;
    prep_kernel<<<(NTAB * 64 / 256) + S1 + S2 + 1152 + 128, 256>>>(
        x_a, x_v, dW1, dW2, dW3, aW1, aW2, aW3, src, BA, E);

    // 2) scan
    scan_kernel<<<1, 512>>>(A);

    // 3) fused 3-layer MLP (both chains) + payload-scatter aux
    const int nA = BA / 64;
    const int nT = NTAB / 64;
    Chain ca = { xa_h, xa_l, wh + 3 * SLOT, wh + 4 * SLOT, wh + 5 * SLOT, ab1, ab2, ab3 };
    Chain ct = { te_h, te_l, wh + 0 * SLOT, wh + 1 * SLOT, wh + 2 * SLOT, db1, db2, db3 };
    fused_kernel<<<nA + nT + 128, 512, FSMEM>>>(ca, ct, nA, nT,
                                                src, dst, r_ij, E, A, BA);

    // 4) gather (64 threads per atom; re-zeroes g_cnt for next replay)
    float* out_a = (float*)d_out;
    float* out_v = (float*)d_out + (size_t)BA * NFEAT;
    gather_kernel<<<A, 64>>>((const uint4*)tp, (const uint4*)pk,
                             (const float4*)sep, (const int*)sdst, out_a, out_v, A);
}

// round 16
// speedup vs baseline: 1.4758x; 1.0955x over previous
#include <cuda_runtime.h>
#include <cuda_fp16.h>
#include <cstdint>

#define NFEAT 64
#define NHID  256
#define EMAX  320000
#define AMAX  10000
#define BAMAX 40000
#define EPS_F 0.1f
#define COEF0 0.31415926535897931f   // pi / R0, R0 = 10
#define NTAB  4096
#define DMAX  10.0f
#define TSCALE ((float)NTAB / DMAX)
#define SLOT  (256 * 256)

// ---------------- scratch (device globals; zero-initialized at load) ----------
__device__ __half g_te_h[(size_t)NTAB * 64];
__device__ __half g_te_l[(size_t)NTAB * 64];
__device__ __half g_xa_h[(size_t)BAMAX * 64];
__device__ __half g_xa_l[(size_t)BAMAX * 64];
__device__ __half g_tp[(size_t)NTAB * 64 * 8];    // paired table records
__device__ __half g_pk[(size_t)BAMAX * 64 * 8];   // packed row records
__device__ float4 g_sep[EMAX];
__device__ int    g_sdst[EMAX];
__device__ __half g_wh[6 * SLOT];
__device__ int g_cnt[AMAX + 1];                    // zeroed by gather each run
__device__ int g_off[AMAX + 1];
__device__ int g_pos[AMAX];

// ---------------- PTX helpers -------------------------------------------------
__device__ __forceinline__ uint32_t smem_u32(const void* p) {
    uint32_t a;
    asm("{ .reg .u64 t; cvta.to.shared.u64 t, %1; cvt.u32.u64 %0, t; }" : "=r"(a) : "l"(p));
    return a;
}
#define CP16(saddr, gptr) \
    asm volatile("cp.async.cg.shared.global [%0], [%1], 16;" :: "r"(saddr), "l"(gptr) : "memory")
#define CP_COMMIT asm volatile("cp.async.commit_group;" ::: "memory")
#define CP_WAIT0 asm volatile("cp.async.wait_group 0;" ::: "memory")
#define CP_WAIT1 asm volatile("cp.async.wait_group 1;" ::: "memory")

__device__ __forceinline__ void ldsm_x4(uint32_t* r, uint32_t addr) {
    asm volatile("ldmatrix.sync.aligned.m8n8.x4.shared.b16 {%0,%1,%2,%3}, [%4];"
                 : "=r"(r[0]), "=r"(r[1]), "=r"(r[2]), "=r"(r[3]) : "r"(addr));
}
__device__ __forceinline__ void mma16816(float* c, const uint32_t* a, uint32_t b0, uint32_t b1) {
    asm volatile("mma.sync.aligned.m16n8k16.row.col.f32.f16.f16.f32 "
                 "{%0,%1,%2,%3}, {%4,%5,%6,%7}, {%8,%9}, {%0,%1,%2,%3};"
                 : "+f"(c[0]), "+f"(c[1]), "+f"(c[2]), "+f"(c[3])
                 : "r"(a[0]), "r"(a[1]), "r"(a[2]), "r"(a[3]), "r"(b0), "r"(b1));
}
__device__ __forceinline__ void split_h(float v, __half& h, __half& l) {
    h = __float2half_rn(v);
    l = __float2half_rn(v - __half2float(h));
}

// ---------------- scan (512 threads) ------------------------------------------
__global__ void scan_kernel(int A) {
    __shared__ int sh[512];
    int tid = threadIdx.x;
    int chunk = (A + 511) >> 9;
    int base = tid * chunk;
    int sum = 0;
    for (int j = 0; j < chunk; j++) {
        int idx = base + j;
        if (idx < A) sum += g_cnt[idx];
    }
    sh[tid] = sum;
    __syncthreads();
    for (int off = 1; off < 512; off <<= 1) {
        int v = 0;
        if (tid >= off) v = sh[tid - off];
        __syncthreads();
        sh[tid] += v;
        __syncthreads();
    }
    int run = (tid == 0) ? 0 : sh[tid - 1];
    for (int j = 0; j < chunk; j++) {
        int idx = base + j;
        if (idx < A) {
            g_off[idx] = run;
            g_pos[idx] = run;
            run += g_cnt[idx];
        }
    }
    if (base < A && A <= base + chunk) g_off[A] = run;
}

// ---------------- prep: tencode + split(x_a,f4) + wtrans + xv-pack + hist -----
__global__ void prep_kernel(
    const float* __restrict__ x_a, const float* __restrict__ x_v,
    const float* __restrict__ dW1, const float* __restrict__ dW2, const float* __restrict__ dW3,
    const float* __restrict__ aW1, const float* __restrict__ aW2, const float* __restrict__ aW3,
    const int* __restrict__ src, int BA, int E)
{
    const int tid = threadIdx.x;
    int bid = blockIdx.x;
    const int S0 = NTAB * 64 / 256;
    const int S1 = (BA * 64) / 1024;
    const int S2 = (BA * 64) / 512;

    if (bid < S0) {
        int t = bid * 256 + tid;
        int k = t >> 6, j = t & 63;
        float d = (float)k * (DMAX / (float)NTAB);
        int kk = j & 31;
        float ph = (float)(1 + (kk >> 1)) * COEF0 * d;
        float v = (j < 32) ? cosf(ph) : sinf(ph);
        __half h, l;
        split_h(v, h, l);
        g_te_h[t] = h; g_te_l[t] = l;
        return;
    }
    bid -= S0;
    if (bid < S1) {
        int t = bid * 256 + tid;
        float4 v4 = ((const float4*)x_a)[t];
        __half h0, l0, h1, l1, h2, l2, h3, l3;
        split_h(v4.x, h0, l0); split_h(v4.y, h1, l1);
        split_h(v4.z, h2, l2); split_h(v4.w, h3, l3);
        __half2* dh = (__half2*)&g_xa_h[(size_t)t * 4];
        __half2* dl = (__half2*)&g_xa_l[(size_t)t * 4];
        dh[0] = __halves2half2(h0, h1); dh[1] = __halves2half2(h2, h3);
        dl[0] = __halves2half2(l0, l1); dl[1] = __halves2half2(l2, l3);
        return;
    }
    bid -= S1;
    if (bid < S2) {
        int t0 = (bid * 256 + tid) * 2;
#pragma unroll
        for (int u = 0; u < 2; u++) {
            int t = t0 + u;
            float v0 = x_v[(size_t)t * 3 + 0];
            float v1 = x_v[(size_t)t * 3 + 1];
            float v2 = x_v[(size_t)t * 3 + 2];
            __half2* d2 = (__half2*)&g_pk[(size_t)t * 8 + 4];
            d2[0] = __floats2half2_rn(v0, v1);
            d2[1] = __floats2half2_rn(v2, 0.f);
        }
        return;
    }
    bid -= S2;
    if (bid < 1152) {
        const float* W; int K, slot;
        if      (bid < 64)  { W = dW1; K = 64;  slot = 0; }
        else if (bid < 320) { W = dW2; K = 256; slot = 1; bid -= 64; }
        else if (bid < 576) { W = dW3; K = 256; slot = 2; bid -= 320; }
        else if (bid < 640) { W = aW1; K = 64;  slot = 3; bid -= 576; }
        else if (bid < 896) { W = aW2; K = 256; slot = 4; bid -= 640; }
        else                { W = aW3; K = 256; slot = 5; bid -= 896; }
        int t = bid * 256 + tid;
        int n = t & 255, k = t >> 8;
        g_wh[(size_t)slot * SLOT + (size_t)n * K + k] =
            __float2half_rn(W[(size_t)k * 256 + n]);
        return;
    }
    bid -= 1152;
    for (int t = bid * 256 + tid; t < E; t += 128 * 256)
        atomicAdd(&g_cnt[src[t]], 1);
}

// ---------------- fused 3-layer MLP kernel ------------------------------------
// Layer-1 input hi/lo (from fp32); layers 2/3 single-fp16 activations.
// SMEM map (bytes):
//   XA 0       (L1 out, pitch 528; reused as record staging in L3 epilogue)
//   XB 33792   (L1 input staging hi@0/lo@+9216, pitch 144; then L2 out pitch 528)
//   BST0 67584  BST1 104448  (B stream, 36864 each)
#define XROWB 528
#define XA_OFF 0
#define XB_OFF 33792
#define INLO  9216
#define BST0  67584
#define BST1  104448
#define FSMEM 141312
#define BROWB 144
#define NSTEP 9

struct Chain {
    const __half* inh; const __half* inl;
    const __half* W1; const __half* W2; const __half* W3;
    const float* b1; const float* b2; const float* b3;
};

__global__ void __launch_bounds__(512, 1) fused_kernel(
    Chain ca, Chain ct, int nA, int nT,
    const int* __restrict__ src, const int* __restrict__ dst,
    const float* __restrict__ r_ij,
    int E, int A, int BA)
{
    extern __shared__ char smem[];
    const int tid = threadIdx.x;
    int bid = blockIdx.x;

    if (bid >= nA + nT) {
        int abid = bid - (nA + nT);
        for (int t = abid * 512 + tid; t < E; t += 128 * 512) {
            float rx = r_ij[(size_t)t * 3 + 0];
            float ry = r_ij[(size_t)t * 3 + 1];
            float rz = r_ij[(size_t)t * 3 + 2];
            float d2s = rx * rx + ry * ry + rz * rz;
            float d = sqrtf(d2s);
            float inv = rsqrtf(EPS_F + d2s);
            float idxf = d * TSCALE;
            if (idxf > (float)(NTAB - 1) - 1e-3f) idxf = (float)(NTAB - 1) - 1e-3f;
            int pp = atomicAdd(&g_pos[src[t]], 1);
            g_sep[pp] = make_float4(rx * inv, ry * inv, rz * inv, idxf);
            g_sdst[pp] = dst[t];
        }
        return;
    }

    const bool isA = bid < nA;
    const Chain C = isA ? ca : ct;
    const int row0 = (isA ? bid : bid - nA) * 64;

    const uint32_t sbase = smem_u32(smem);
    const int lane = tid & 31;
    const int wid = tid >> 5;
    const int warp_m = wid & 3;
    const int warp_n = wid >> 2;

    const uint32_t arow = (uint32_t)(warp_m * 16 + (lane & 15));
    const uint32_t asub = (uint32_t)((lane >> 4) << 4);
    const uint32_t boff = (uint32_t)(warp_n * 64 + (lane & 7) + ((lane >> 4) << 3)) * BROWB
                        + (((lane >> 3) & 1) << 4);

    const __half* Ws[3] = { C.W1, C.W2, C.W3 };
    const float* Bs[3] = { C.b1, C.b2, C.b3 };

    // L1 input staging (hi/lo, pitch 144) into XB region
    {
        int r = tid >> 3, cs = tid & 7;
        size_t ga = (size_t)(row0 + r) * 64 + cs * 8;
        uint32_t so = (uint32_t)r * BROWB + cs * 16;
        CP16(sbase + XB_OFF + so, C.inh + ga);
        CP16(sbase + XB_OFF + INLO + so, C.inl + ga);
    }

    auto load_B = [&](int slot, int s) {
        int L, kb, K;
        if (s == 0)     { L = 0; kb = 0;            K = 64; }
        else if (s < 5) { L = 1; kb = (s - 1) * 64; K = 256; }
        else            { L = 2; kb = (s - 5) * 64; K = 256; }
        const __half* W = Ws[L];
        uint32_t sb = sbase + (slot ? BST1 : BST0);
#pragma unroll
        for (int it = 0; it < 4; it++) {
            int idx = tid + it * 512;
            int r = idx >> 3, cs = idx & 7;
            CP16(sb + (uint32_t)r * BROWB + cs * 16,
                 W + (size_t)r * K + kb + cs * 8);
        }
    };

    load_B(0, 0); CP_COMMIT;
    load_B(1, 1); CP_COMMIT;

    float acc[8][4];

    for (int s = 0; s < NSTEP; s++) {
        int L, c, last;
        if (s == 0)     { L = 0; c = 0;     last = 1; }
        else if (s < 5) { L = 1; c = s - 1; last = (c == 3); }
        else            { L = 2; c = s - 5; last = (c == 3); }

        if (s + 1 < NSTEP) { CP_WAIT1; } else { CP_WAIT0; }
        __syncthreads();

        if (c == 0) {
#pragma unroll
            for (int tn = 0; tn < 8; tn++)
#pragma unroll
                for (int j = 0; j < 4; j++) acc[tn][j] = 0.f;
        }

        uint32_t ab;
        if (L == 0) ab = sbase + XB_OFF + arow * BROWB + asub;
        else {
            uint32_t xh = (L == 1) ? XA_OFF : XB_OFF;
            ab = sbase + xh + arow * XROWB + asub + c * 128;
        }
        const uint32_t bbb = sbase + ((s & 1) ? BST1 : BST0) + boff;

#pragma unroll
        for (int ks = 0; ks < 4; ks++) {
            uint32_t ah[4], bb[4][4];
            ldsm_x4(ah, ab + ks * 32);
#pragma unroll
            for (int tg = 0; tg < 4; tg++)
                ldsm_x4(bb[tg], bbb + tg * 16 * BROWB + ks * 32);
#pragma unroll
            for (int tn = 0; tn < 8; tn++) {
                uint32_t b0 = bb[tn >> 1][(tn & 1) * 2];
                uint32_t b1 = bb[tn >> 1][(tn & 1) * 2 + 1];
                mma16816(acc[tn], ah, b0, b1);
            }
            if (L == 0) {   // layer-1 extra lo pass (input from fp32 split)
                uint32_t al[4];
                ldsm_x4(al, ab + INLO + ks * 32);
#pragma unroll
                for (int tn = 0; tn < 8; tn++) {
                    uint32_t b0 = bb[tn >> 1][(tn & 1) * 2];
                    uint32_t b1 = bb[tn >> 1][(tn & 1) * 2 + 1];
                    mma16816(acc[tn], al, b0, b1);
                }
            }
        }

        if (last) {
            const int act = (L < 2);
#pragma unroll
            for (int tn = 0; tn < 8; tn++) {
                int gcol = warp_n * 64 + tn * 8 + 2 * (lane & 3);
                int r0 = warp_m * 16 + (lane >> 2);
                float b0 = __ldg(&Bs[L][gcol]);
                float b1 = __ldg(&Bs[L][gcol + 1]);
                float v0 = acc[tn][0] + b0;
                float v1 = acc[tn][1] + b1;
                float v2 = acc[tn][2] + b0;
                float v3 = acc[tn][3] + b1;
                if (act) {
                    v0 = v0 / (1.f + __expf(-v0));
                    v1 = v1 / (1.f + __expf(-v1));
                    v2 = v2 / (1.f + __expf(-v2));
                    v3 = v3 / (1.f + __expf(-v3));
                }
                if (L < 2) {
                    const uint32_t xh = (L == 0) ? XA_OFF : XB_OFF;
                    char* base = smem + xh;
                    *(__half2*)(base + (size_t)r0 * XROWB + gcol * 2) =
                        __floats2half2_rn(v0, v1);
                    *(__half2*)(base + (size_t)(r0 + 8) * XROWB + gcol * 2) =
                        __floats2half2_rn(v2, v3);
                } else {
                    __half* sg = (__half*)smem;
                    int f = gcol & 63, role = gcol >> 6;
                    sg[r0 * 260 + f * 4 + role]             = __float2half_rn(v0);
                    sg[r0 * 260 + (f + 1) * 4 + role]       = __float2half_rn(v1);
                    sg[(r0 + 8) * 260 + f * 4 + role]       = __float2half_rn(v2);
                    sg[(r0 + 8) * 260 + (f + 1) * 4 + role] = __float2half_rn(v3);
                }
            }
        }

        if (s + 2 < NSTEP) {
            __syncthreads();
            load_B(s & 1, s + 2);
            CP_COMMIT;
        }
    }

    // final record writes
    __syncthreads();
    __half* sg = (__half*)smem;
    if (isA) {
#pragma unroll
        for (int i = 0; i < 8; i++) {
            int idx = tid + i * 512;
            int rr = idx >> 6, f = idx & 63;
            uint2 w = *(uint2*)&sg[rr * 260 + f * 4];
            *(uint2*)((char*)g_pk + ((size_t)(row0 + rr) * 64 + f) * 16) = w;
        }
    } else {
#pragma unroll
        for (int i = 0; i < 8; i++) {
            int idx = tid + i * 512;
            int rr = idx >> 6, f = idx & 63;
            char* rec = (char*)g_tp + (((size_t)(row0 + rr)) * 64 + f) * 16;
            uint2 lo = *(uint2*)&sg[rr * 260 + f * 4];
            *(uint2*)rec = lo;
            if (rr < 63) {
                uint2 hi = *(uint2*)&sg[(rr + 1) * 260 + f * 4];
                *(uint2*)(rec + 8) = hi;
            }
        }
        if (row0 > 0 && tid < 64) {
            uint2 w0 = *(uint2*)&sg[0 * 260 + tid * 4];
            *(uint2*)((char*)g_tp + ((size_t)(row0 - 1) * 64 + tid) * 16 + 8) = w0;
        }
    }
}

// ---------------- per-atom gather: 64 threads, batch-loop dedups lerp ---------
__global__ __launch_bounds__(64) void gather_kernel(
    const uint4* __restrict__ TP,
    const uint4* __restrict__ PK,
    const float4* __restrict__ SEP,
    const int* __restrict__ SDST,
    float* __restrict__ out_a, float* __restrict__ out_v, int A)
{
    int a = blockIdx.x;
    int f = threadIdx.x;
    int p0 = g_off[a];
    int p1 = g_off[a + 1];

    if (f == 0) {
        g_cnt[a] = 0;
        if (a == 0) g_cnt[A] = 0;
    }

    float av[4][3];
    float aa[4];
#pragma unroll
    for (int b = 0; b < 4; b++) {
        av[b][0] = 0.f; av[b][1] = 0.f; av[b][2] = 0.f; aa[b] = 0.f;
    }

#pragma unroll 2
    for (int p = p0; p < p1; ++p) {
        float4 ed = __ldg(&SEP[p]);
        int dd = __ldg(&SDST[p]);
        float d0 = ed.x, d1 = ed.y, d2 = ed.z;
        int k = (int)ed.w;
        float w = ed.w - (float)k;

        uint4 tv = __ldg(&TP[(size_t)k * 64 + f]);
        float2 t0a = __half22float2(*(__half2*)&tv.x);
        float2 t0b = __half22float2(*(__half2*)&tv.y);
        float2 t1a = __half22float2(*(__half2*)&tv.z);
        float2 t1b = __half22float2(*(__half2*)&tv.w);
        float q0t = fmaf(w, t1a.x - t0a.x, t0a.x);
        float q1t = fmaf(w, t1a.y - t0a.y, t0a.y);
        float q2t = fmaf(w, t1b.x - t0b.x, t0b.x);
        float q3t = fmaf(w, t1b.y - t0b.y, t0b.y);

        size_t rbase = (size_t)dd * 64 + f;
#pragma unroll
        for (int b = 0; b < 4; b++) {
            uint4 pk = __ldg(&PK[rbase + (size_t)b * A * 64]);
            __half2 pra = *(__half2*)&pk.x;
            __half2 prb = *(__half2*)&pk.y;
            float q0 = q0t * __low2float(pra);
            float q1 = q1t * __high2float(pra);
            float q2 = q2t * __low2float(prb);
            float q3 = q3t * __high2float(prb);

            float2 va = __half22float2(*(__half2*)&pk.z);
            float v2f = __low2float(*(__half2*)&pk.w);
            float v0 = va.x, v1 = va.y, v2 = v2f;
            float c0 = v1 * d2 - v2 * d1;
            float c1 = v2 * d0 - v0 * d2;
            float c2 = v0 * d1 - v1 * d0;
            av[b][0] += v0 * q0 + c0 * q1 + d0 * q2;
            av[b][1] += v1 * q0 + c1 * q1 + d1 * q2;
            av[b][2] += v2 * q0 + c2 * q1 + d2 * q2;
            aa[b]    += q3;
        }
    }

#pragma unroll
    for (int b = 0; b < 4; b++) {
        out_a[(size_t)(b * A + a) * 64 + f] = aa[b];
        float* OV = out_v + (size_t)((b * A + a) * 64 + f) * 3;
        OV[0] = av[b][0];
        OV[1] = av[b][1];
        OV[2] = av[b][2];
    }
}

// ---------------- launch ------------------------------------------------------
extern "C" void kernel_launch(void* const* d_in, const int* in_sizes, int n_in,
                              void* d_out, int out_size) {
    const float* x_a  = (const float*)d_in[0];
    const float* x_v  = (const float*)d_in[1];
    const float* r_ij = (const float*)d_in[2];
    const int*   src  = (const int*)d_in[3];
    const int*   dst  = (const int*)d_in[4];
    const float* dW1 = (const float*)d_in[5];
    const float* db1 = (const float*)d_in[6];
    const float* dW2 = (const float*)d_in[7];
    const float* db2 = (const float*)d_in[8];
    const float* dW3 = (const float*)d_in[9];
    const float* db3 = (const float*)d_in[10];
    const float* aW1 = (const float*)d_in[11];
    const float* ab1 = (const float*)d_in[12];
    const float* aW2 = (const float*)d_in[13];
    const float* ab2 = (const float*)d_in[14];
    const float* aW3 = (const float*)d_in[15];
    const float* ab3 = (const float*)d_in[16];

    const int E  = in_sizes[3];
    const int BA = in_sizes[0] / NFEAT;
    const int A  = BA / 4;                 // B = 4

    __half *te_h, *te_l, *xa_h, *xa_l, *wh, *tp, *pk;
    float4 *sep;
    int *sdst;
    cudaGetSymbolAddress((void**)&te_h, g_te_h);
    cudaGetSymbolAddress((void**)&te_l, g_te_l);
    cudaGetSymbolAddress((void**)&xa_h, g_xa_h);
    cudaGetSymbolAddress((void**)&xa_l, g_xa_l);
    cudaGetSymbolAddress((void**)&wh, g_wh);
    cudaGetSymbolAddress((void**)&tp, g_tp);
    cudaGetSymbolAddress((void**)&pk, g_pk);
    cudaGetSymbolAddress((void**)&sep, g_sep);
    cudaGetSymbolAddress((void**)&sdst, g_sdst);

    cudaFuncSetAttribute(fused_kernel, cudaFuncAttributeMaxDynamicSharedMemorySize, FSMEM);

    // 1) prep
    const int S1 = (BA * 64) / 1024;
    const int S2 = (BA * 64) / 512;
    prep_kernel<<<(NTAB * 64 / 256) + S1 + S2 + 1152 + 128, 256>>>(
        x_a, x_v, dW1, dW2, dW3, aW1, aW2, aW3, src, BA, E);

    // 2) scan
    scan_kernel<<<1, 512>>>(A);

    // 3) fused 3-layer MLP (both chains) + payload-scatter aux
    const int nA = BA / 64;
    const int nT = NTAB / 64;
    Chain ca = { xa_h, xa_l, wh + 3 * SLOT, wh + 4 * SLOT, wh + 5 * SLOT, ab1, ab2, ab3 };
    Chain ct = { te_h, te_l, wh + 0 * SLOT, wh + 1 * SLOT, wh + 2 * SLOT, db1, db2, db3 };
    fused_kernel<<<nA + nT + 128, 512, FSMEM>>>(ca, ct, nA, nT,
                                                src, dst, r_ij, E, A, BA);

    // 4) gather (64 threads per atom; re-zeroes g_cnt for next replay)
    float* out_a = (float*)d_out;
    float* out_v = (float*)d_out + (size_t)BA * NFEAT;
    gather_kernel<<<A, 64>>>((const uint4*)tp, (const uint4*)pk,
                             (const float4*)sep, (const int*)sdst, out_a, out_v, A);
}